// round 9
// baseline (speedup 1.0000x reference)
#include <cuda_runtime.h>
#include <cuda_fp16.h>
#include <math.h>
#include <stdint.h>

#define Bsz 4
#define NG  8192
#define Cdim 256
#define Hh  128
#define Ww  128
#define NT  512
#define EPSLN 1e-5f
#define ATTN_SCALE 0.17677669529663687f

__device__ float  g_tf [Bsz*NT*Cdim];
__device__ float  g_kv [Bsz*NT*512];             // [row][k(256) | v(256)]
__device__ float  g_q  [Bsz*NG*Cdim];            // q-proj -> mha-out -> sampled S
__device__ float  g_ctx[Bsz*NG*Cdim];            // attn ctx -> LN output
__device__ __half g_vt [(size_t)Bsz*Hh*Ww*Cdim]; // value transposed (B,H,W,C), fp16
__device__ float  g_oa [Bsz*NG*96];
__device__ float  g_wc [96*Cdim];
__device__ float  g_bc [96];

// ---- merged trajectory projection + weight concat ----
__global__ __launch_bounds__(256) void k_prep(const float* __restrict__ tp,
                                              const float* __restrict__ tw,
                                              const float* __restrict__ tb,
                                              const float* __restrict__ ow,
                                              const float* __restrict__ ob,
                                              const float* __restrict__ aw,
                                              const float* __restrict__ ab) {
    int bi = blockIdx.x, t = threadIdx.x;
    if (bi < Bsz * NT) {
        g_tf[(size_t)bi * Cdim + t] =
            fmaf(tp[bi * 2], tw[t * 2], fmaf(tp[bi * 2 + 1], tw[t * 2 + 1], tb[t]));
    } else {
        int i = (bi - Bsz * NT) * 256 + t;
        if (i < 64 * 256)                 g_wc[i] = ow[i];
        else if (i < 96 * 256)            g_wc[i] = aw[i - 64 * 256];
        else if (i < 96 * 256 + 64)       g_bc[i - 96 * 256] = ob[i - 96 * 256];
        else if (i < 96 * 256 + 96)       g_bc[i - 96 * 256] = ab[i - 96 * 256 - 64];
    }
}

// ---- scalar fp32 GEMM (kept for k/v projection only) ----
__global__ __launch_bounds__(256) void gemm_bias(const float* __restrict__ X,
                                                 const float* __restrict__ W,
                                                 const float* __restrict__ bias,
                                                 float* __restrict__ Y, int N) {
    __shared__ __align__(16) float As[16][132];
    __shared__ __align__(16) float Bs[16][68];
    int tid = threadIdx.x;
    int row0 = blockIdx.y * 128, n0 = blockIdx.x * 64;
    int rg = tid >> 4, cg = tid & 15;
    float acc[8][4];
#pragma unroll
    for (int i = 0; i < 8; i++)
#pragma unroll
        for (int j = 0; j < 4; j++) acc[i][j] = 0.f;

    int ar = tid >> 1, akq = (tid & 1) * 8;
    int bn = tid >> 2, bkq = (tid & 3) * 4;
    bool bvalid = (n0 + bn) < N;
    const float* Xp = X + (size_t)(row0 + ar) * 256 + akq;
    const float* Wp = W + (size_t)(n0 + bn) * 256 + bkq;

    for (int kt = 0; kt < 16; kt++) {
        int k0 = kt * 16;
        float4 a0 = *(const float4*)(Xp + k0);
        float4 a1 = *(const float4*)(Xp + k0 + 4);
        float4 b0 = bvalid ? *(const float4*)(Wp + k0) : make_float4(0.f, 0.f, 0.f, 0.f);
        As[akq + 0][ar] = a0.x; As[akq + 1][ar] = a0.y;
        As[akq + 2][ar] = a0.z; As[akq + 3][ar] = a0.w;
        As[akq + 4][ar] = a1.x; As[akq + 5][ar] = a1.y;
        As[akq + 6][ar] = a1.z; As[akq + 7][ar] = a1.w;
        Bs[bkq + 0][bn] = b0.x; Bs[bkq + 1][bn] = b0.y;
        Bs[bkq + 2][bn] = b0.z; Bs[bkq + 3][bn] = b0.w;
        __syncthreads();
#pragma unroll
        for (int kk = 0; kk < 16; kk++) {
            float4 av0 = *(const float4*)&As[kk][rg * 8];
            float4 av1 = *(const float4*)&As[kk][rg * 8 + 4];
            float4 bv  = *(const float4*)&Bs[kk][cg * 4];
            float a[8] = {av0.x, av0.y, av0.z, av0.w, av1.x, av1.y, av1.z, av1.w};
            float bb[4] = {bv.x, bv.y, bv.z, bv.w};
#pragma unroll
            for (int i = 0; i < 8; i++)
#pragma unroll
                for (int j = 0; j < 4; j++) acc[i][j] = fmaf(a[i], bb[j], acc[i][j]);
        }
        __syncthreads();
    }
    int nc = n0 + cg * 4;
    if (nc < N) {
        float4 bb = *(const float4*)(bias + nc);
#pragma unroll
        for (int i = 0; i < 8; i++) {
            float4 o;
            o.x = acc[i][0] + bb.x; o.y = acc[i][1] + bb.y;
            o.z = acc[i][2] + bb.z; o.w = acc[i][3] + bb.w;
            *(float4*)(Y + (size_t)(row0 + rg * 8 + i) * N + nc) = o;
        }
    }
}

__device__ __forceinline__ uint32_t f2tf32(float x) {
    uint32_t r; asm("cvt.rna.tf32.f32 %0, %1;" : "=r"(r) : "f"(x)); return r;
}
__device__ __forceinline__ void split_tf32(float x, uint32_t& h, uint32_t& l) {
    uint32_t hb; asm("cvt.rna.tf32.f32 %0, %1;" : "=r"(hb) : "f"(x));
    float r = x - __uint_as_float(hb);
    uint32_t lb; asm("cvt.rna.tf32.f32 %0, %1;" : "=r"(lb) : "f"(r));
    h = hb; l = lb;
}
#define MMA_TF32(acc, a0, a1, a2, a3, b0, b1) \
    asm volatile("mma.sync.aligned.m16n8k8.row.col.f32.tf32.tf32.f32 " \
        "{%0,%1,%2,%3}, {%4,%5,%6,%7}, {%8,%9}, {%0,%1,%2,%3};" \
        : "+f"((acc)[0]), "+f"((acc)[1]), "+f"((acc)[2]), "+f"((acc)[3]) \
        : "r"(a0), "r"(a1), "r"(a2), "r"(a3), "r"(b0), "r"(b1))

// ---- 3xTF32 GEMM (fp32-grade precision on tensor pipe): Y = X[Rx256] @ W[Nx256]^T + bias ----
// BM=128 BN=64 BK=32, 256 threads, warp = 16-row stripe.
__global__ __launch_bounds__(256) void gemm_mma3(const float* __restrict__ X,
                                                 const float* __restrict__ W,
                                                 const float* __restrict__ bias,
                                                 float* __restrict__ Y, int N) {
    extern __shared__ uint32_t smu[];
    uint32_t (*Ah)[132] = (uint32_t(*)[132])smu;            // 32x132
    uint32_t (*Al)[132] = Ah + 32;
    uint32_t (*Bh)[68]  = (uint32_t(*)[68])(smu + 2 * 32 * 132);
    uint32_t (*Bl)[68]  = Bh + 32;
    int tid = threadIdx.x;
    int row0 = blockIdx.y * 128, n0b = blockIdx.x * 64;
    int w = tid >> 5, lane = tid & 31, grp = lane >> 2, qid = lane & 3;
    float acc[8][4];
#pragma unroll
    for (int j = 0; j < 8; j++)
#pragma unroll
        for (int i = 0; i < 4; i++) acc[j][i] = 0.f;

    int ar = tid >> 1, ak = (tid & 1) * 16;
    int br = tid >> 2, bk = (tid & 3) * 8;
    bool bvalid = (n0b + br) < N;
    const float* Xp = X + (size_t)(row0 + ar) * 256 + ak;
    const float* Wp = W + (size_t)(bvalid ? (n0b + br) : 0) * 256 + bk;

    for (int kt = 0; kt < 8; kt++) {
        int k0 = kt * 32;
#pragma unroll
        for (int i = 0; i < 4; i++) {
            float4 v = *(const float4*)(Xp + k0 + i * 4);
            float e[4] = {v.x, v.y, v.z, v.w};
#pragma unroll
            for (int q = 0; q < 4; q++) {
                uint32_t h, l; split_tf32(e[q], h, l);
                Ah[ak + i * 4 + q][ar] = h; Al[ak + i * 4 + q][ar] = l;
            }
        }
#pragma unroll
        for (int i = 0; i < 2; i++) {
            float4 v = bvalid ? *(const float4*)(Wp + k0 + i * 4)
                              : make_float4(0.f, 0.f, 0.f, 0.f);
            float e[4] = {v.x, v.y, v.z, v.w};
#pragma unroll
            for (int q = 0; q < 4; q++) {
                uint32_t h, l; split_tf32(e[q], h, l);
                Bh[bk + i * 4 + q][br] = h; Bl[bk + i * 4 + q][br] = l;
            }
        }
        __syncthreads();
#pragma unroll
        for (int kk = 0; kk < 4; kk++) {
            int kb = kk * 8;
            uint32_t ah0 = Ah[kb + qid][w * 16 + grp];
            uint32_t ah1 = Ah[kb + qid][w * 16 + grp + 8];
            uint32_t ah2 = Ah[kb + qid + 4][w * 16 + grp];
            uint32_t ah3 = Ah[kb + qid + 4][w * 16 + grp + 8];
            uint32_t al0 = Al[kb + qid][w * 16 + grp];
            uint32_t al1 = Al[kb + qid][w * 16 + grp + 8];
            uint32_t al2 = Al[kb + qid + 4][w * 16 + grp];
            uint32_t al3 = Al[kb + qid + 4][w * 16 + grp + 8];
#pragma unroll
            for (int j = 0; j < 8; j++) {
                uint32_t bh0 = Bh[kb + qid][j * 8 + grp];
                uint32_t bh1 = Bh[kb + qid + 4][j * 8 + grp];
                uint32_t bl0 = Bl[kb + qid][j * 8 + grp];
                uint32_t bl1 = Bl[kb + qid + 4][j * 8 + grp];
                MMA_TF32(acc[j], ah0, ah1, ah2, ah3, bl0, bl1);   // hi*lo
                MMA_TF32(acc[j], al0, al1, al2, al3, bh0, bh1);   // lo*hi
                MMA_TF32(acc[j], ah0, ah1, ah2, ah3, bh0, bh1);   // hi*hi
            }
        }
        __syncthreads();
    }
    int r = row0 + w * 16 + grp;
#pragma unroll
    for (int j = 0; j < 8; j++) {
        int c = n0b + j * 8 + qid * 2;
        if (c < N) {
            float2 bb = *(const float2*)(bias + c);
            float2 o0 = {acc[j][0] + bb.x, acc[j][1] + bb.y};
            float2 o1 = {acc[j][2] + bb.x, acc[j][3] + bb.y};
            *(float2*)(Y + (size_t)r * N + c) = o0;
            *(float2*)(Y + (size_t)(r + 8) * N + c) = o1;
        }
    }
}

// ---- single-pass tf32 mma GEMM (final projection, 1x error path), N=256 fixed ----
__global__ __launch_bounds__(256) void gemm_mma(const float* __restrict__ X,
                                                const float* __restrict__ W,
                                                const float* __restrict__ bias,
                                                float* __restrict__ Y) {
    __shared__ uint32_t As[32][132];
    __shared__ uint32_t Bs[32][68];
    int tid = threadIdx.x;
    int row0 = blockIdx.y * 128, n0b = blockIdx.x * 64;
    int w = tid >> 5, lane = tid & 31, grp = lane >> 2, qid = lane & 3;
    float acc[8][4];
#pragma unroll
    for (int j = 0; j < 8; j++)
#pragma unroll
        for (int i = 0; i < 4; i++) acc[j][i] = 0.f;

    int ar = tid >> 1, ak = (tid & 1) * 16;
    int br = tid >> 2, bk = (tid & 3) * 8;
    const float* Xp = X + (size_t)(row0 + ar) * 256 + ak;
    const float* Wp = W + (size_t)(n0b + br) * 256 + bk;

    for (int kt = 0; kt < 8; kt++) {
        int k0 = kt * 32;
#pragma unroll
        for (int i = 0; i < 4; i++) {
            float4 v = *(const float4*)(Xp + k0 + i * 4);
            As[ak + i * 4 + 0][ar] = f2tf32(v.x); As[ak + i * 4 + 1][ar] = f2tf32(v.y);
            As[ak + i * 4 + 2][ar] = f2tf32(v.z); As[ak + i * 4 + 3][ar] = f2tf32(v.w);
        }
#pragma unroll
        for (int i = 0; i < 2; i++) {
            float4 v = *(const float4*)(Wp + k0 + i * 4);
            Bs[bk + i * 4 + 0][br] = f2tf32(v.x); Bs[bk + i * 4 + 1][br] = f2tf32(v.y);
            Bs[bk + i * 4 + 2][br] = f2tf32(v.z); Bs[bk + i * 4 + 3][br] = f2tf32(v.w);
        }
        __syncthreads();
#pragma unroll
        for (int kk = 0; kk < 4; kk++) {
            int kb = kk * 8;
            uint32_t a0 = As[kb + qid][w * 16 + grp];
            uint32_t a1 = As[kb + qid][w * 16 + grp + 8];
            uint32_t a2 = As[kb + qid + 4][w * 16 + grp];
            uint32_t a3 = As[kb + qid + 4][w * 16 + grp + 8];
#pragma unroll
            for (int j = 0; j < 8; j++) {
                uint32_t b0 = Bs[kb + qid][j * 8 + grp];
                uint32_t b1 = Bs[kb + qid + 4][j * 8 + grp];
                MMA_TF32(acc[j], a0, a1, a2, a3, b0, b1);
            }
        }
        __syncthreads();
    }
    int r = row0 + w * 16 + grp;
#pragma unroll
    for (int j = 0; j < 8; j++) {
        int c = n0b + j * 8 + qid * 2;
        float2 bb = *(const float2*)(bias + c);
        float2 o0 = {acc[j][0] + bb.x, acc[j][1] + bb.y};
        float2 o1 = {acc[j][2] + bb.x, acc[j][3] + bb.y};
        *(float2*)(Y + (size_t)r * 256 + c) = o0;
        *(float2*)(Y + (size_t)(r + 8) * 256 + c) = o1;
    }
}

// ---- fused per-(b,m) attention; two 256-key tiles (64KB smem -> 2 CTAs/SM) ----
__global__ __launch_bounds__(256) void k_attn() {
    extern __shared__ __align__(16) float sh[];
    float* Ks = sh;                 // 256*32
    float* Vs = sh + 256 * 32;      // 256*32
    int bi = blockIdx.x;            // 1024 = B * 8 * 32
    int qb = bi & 31, m = (bi >> 5) & 7, b = bi >> 8;
    int tid = threadIdx.x;

    int g = qb * 256 + tid;
    const float4* qp = (const float4*)(g_q + ((size_t)(b * NG + g) * Cdim) + m * 32);
    float4 q4[8];
#pragma unroll
    for (int i = 0; i < 8; i++) {
        float4 t4 = qp[i];
        q4[i].x = t4.x * ATTN_SCALE; q4[i].y = t4.y * ATTN_SCALE;
        q4[i].z = t4.z * ATTN_SCALE; q4[i].w = t4.w * ATTN_SCALE;
    }
    float4 ctx[8];
#pragma unroll
    for (int i = 0; i < 8; i++) ctx[i] = make_float4(0.f, 0.f, 0.f, 0.f);
    float sm = 0.f;

    for (int t0 = 0; t0 < NT; t0 += 256) {
        __syncthreads();
        {
            const float4* kp = (const float4*)(g_kv + ((size_t)(b * NT + t0 + tid) * 512) + m * 32);
            const float4* vp = kp + 64;
            float4* kd = (float4*)(Ks + tid * 32);
            float4* vd = (float4*)(Vs + tid * 32);
#pragma unroll
            for (int i = 0; i < 8; i++) { kd[i] = kp[i]; vd[i] = vp[i]; }
        }
        __syncthreads();
#pragma unroll 2
        for (int t = 0; t < 256; t++) {
            const float4* kp4 = (const float4*)(Ks + t * 32);
            float a0 = 0.f, a1 = 0.f, a2 = 0.f, a3 = 0.f;
#pragma unroll
            for (int i = 0; i < 8; i++) {
                float4 kv = kp4[i];
                a0 = fmaf(q4[i].x, kv.x, a0); a1 = fmaf(q4[i].y, kv.y, a1);
                a2 = fmaf(q4[i].z, kv.z, a2); a3 = fmaf(q4[i].w, kv.w, a3);
            }
            float p = __expf((a0 + a1) + (a2 + a3));
            sm += p;
            const float4* vp4 = (const float4*)(Vs + t * 32);
#pragma unroll
            for (int i = 0; i < 8; i++) {
                float4 vv = vp4[i];
                ctx[i].x = fmaf(p, vv.x, ctx[i].x); ctx[i].y = fmaf(p, vv.y, ctx[i].y);
                ctx[i].z = fmaf(p, vv.z, ctx[i].z); ctx[i].w = fmaf(p, vv.w, ctx[i].w);
            }
        }
    }
    float inv = 1.f / sm;
    float4* op = (float4*)(g_ctx + ((size_t)(b * NG + g) * Cdim) + m * 32);
#pragma unroll
    for (int i = 0; i < 8; i++) {
        float4 o;
        o.x = ctx[i].x * inv; o.y = ctx[i].y * inv;
        o.z = ctx[i].z * inv; o.w = ctx[i].w * inv;
        op[i] = o;
    }
}

// ---- residual + LayerNorm: g_ctx = LN(g_q + query) ----
__global__ __launch_bounds__(256) void k_ln(const float* __restrict__ q_in,
                                            const float* __restrict__ lng,
                                            const float* __restrict__ lnb) {
    int row = blockIdx.x, t = threadIdx.x;
    size_t base = (size_t)row * Cdim + t;
    float x = g_q[base] + q_in[base];
    __shared__ float red[8];
    int lane = t & 31, w = t >> 5;
    float s = x;
#pragma unroll
    for (int o = 16; o; o >>= 1) s += __shfl_xor_sync(0xffffffffu, s, o);
    if (!lane) red[w] = s;
    __syncthreads();
    float tot = 0.f;
#pragma unroll
    for (int i = 0; i < 8; i++) tot += red[i];
    float mu = tot * (1.f / 256.f);
    float d = x - mu;
    __syncthreads();
    float s2 = d * d;
#pragma unroll
    for (int o = 16; o; o >>= 1) s2 += __shfl_xor_sync(0xffffffffu, s2, o);
    if (!lane) red[w] = s2;
    __syncthreads();
    float tot2 = 0.f;
#pragma unroll
    for (int i = 0; i < 8; i++) tot2 += red[i];
    g_ctx[base] = d * rsqrtf(tot2 * (1.f / 256.f) + EPSLN) * lng[t] + lnb[t];
}

// ---- value (B,C,H,W) fp32 -> (B,H,W,C) fp16 ----
__global__ __launch_bounds__(256) void k_transpose(const float* __restrict__ val) {
    __shared__ float tile[32][33];
    int tx = threadIdx.x, ty = threadIdx.y;
    int b = blockIdx.z, y = blockIdx.y;
    int c0 = (blockIdx.x >> 2) * 32, x0 = (blockIdx.x & 3) * 32;
#pragma unroll
    for (int i = 0; i < 4; i++)
        tile[ty + i * 8][tx] = val[(((size_t)(b * Cdim + c0 + ty + i * 8) * Hh + y) * Ww) + x0 + tx];
    __syncthreads();
#pragma unroll
    for (int i = 0; i < 4; i++)
        g_vt[(((size_t)(b * Hh + y) * Ww + x0 + ty + i * 8) * Cdim) + c0 + tx] =
            __float2half(tile[tx][ty + i * 8]);
}

// ---- bilinear corner accumulate (fp16 values, fp32 math) ----
__device__ __forceinline__ void corner(const __half* __restrict__ vb, int x, int y,
                                       int moff, float w, float* acc) {
    if (x < 0 || x >= Ww || y < 0 || y >= Hh) return;
    const uint4* p = (const uint4*)(vb + ((size_t)(y * Ww + x)) * Cdim + moff);
#pragma unroll
    for (int i = 0; i < 4; i++) {
        uint4 u = p[i];
        const __half2* h = (const __half2*)&u;
#pragma unroll
        for (int j = 0; j < 4; j++) {
            float2 f = __half22float2(h[j]);
            acc[i * 8 + j * 2]     = fmaf(w, f.x, acc[i * 8 + j * 2]);
            acc[i * 8 + j * 2 + 1] = fmaf(w, f.y, acc[i * 8 + j * 2 + 1]);
        }
    }
}

// ---- deformable sampling: thread = (query, m); scrambled store into g_q ----
__global__ __launch_bounds__(128) void k_sample(const float* __restrict__ refp) {
    int bi = blockIdx.x;            // 2048 = B * 8 * 64
    int tid = threadIdx.x;
    int b = bi >> 9;
    int m = (bi >> 6) & 7;
    int gg = (bi & 63) * 128 + tid;
    int gh = gg >> 8, gl = gg & 255;
    size_t qidx = (size_t)b * NG + gg;
    float rx = refp[qidx * 2], ry = refp[qidx * 2 + 1];
    const float* oar = g_oa + qidx * 96;

    float a0 = oar[64 + m * 4], a1 = oar[64 + m * 4 + 1];
    float a2 = oar[64 + m * 4 + 2], a3 = oar[64 + m * 4 + 3];
    float amx = fmaxf(fmaxf(a0, a1), fmaxf(a2, a3));
    float e0 = __expf(a0 - amx), e1 = __expf(a1 - amx);
    float e2 = __expf(a2 - amx), e3 = __expf(a3 - amx);
    float inv = 1.f / (e0 + e1 + e2 + e3);
    float aw[4] = {e0 * inv, e1 * inv, e2 * inv, e3 * inv};

    const __half* vb = g_vt + (size_t)b * Hh * Ww * Cdim;
    float acc[32];
#pragma unroll
    for (int i = 0; i < 32; i++) acc[i] = 0.f;

#pragma unroll
    for (int p = 0; p < 4; p++) {
        float gx = (rx + oar[m * 8 + p * 2]) * (float)Ww - 0.5f;
        float gy = (ry + oar[m * 8 + p * 2 + 1]) * (float)Hh - 0.5f;
        float x0f = floorf(gx), y0f = floorf(gy);
        float fx = gx - x0f, fy = gy - y0f;
        int x0 = (int)x0f, y0 = (int)y0f;
        float w = aw[p];
        corner(vb, x0,     y0,     m * 32, (1.f - fx) * (1.f - fy) * w, acc);
        corner(vb, x0 + 1, y0,     m * 32, fx * (1.f - fy) * w, acc);
        corner(vb, x0,     y0 + 1, m * 32, (1.f - fx) * fy * w, acc);
        corner(vb, x0 + 1, y0 + 1, m * 32, fx * fy * w, acc);
    }
    // S[b][ch*256 + m*32 + gh][gl]
    float* S = g_q + (size_t)b * NG * 256 + (size_t)(m * 32 + gh) * 256 + gl;
#pragma unroll
    for (int ch = 0; ch < 32; ch++) S[(size_t)ch * 65536] = acc[ch];
}

extern "C" void kernel_launch(void* const* d_in, const int* in_sizes, int n_in,
                              void* d_out, int out_size) {
    const float* query  = (const float*)d_in[0];
    const float* value  = (const float*)d_in[1];
    const float* refp   = (const float*)d_in[2];
    const float* trajp  = (const float*)d_in[3];
    const float* in_w   = (const float*)d_in[4];
    const float* in_b   = (const float*)d_in[5];
    const float* mha_w  = (const float*)d_in[6];
    const float* mha_b  = (const float*)d_in[7];
    const float* ln_g   = (const float*)d_in[8];
    const float* ln_b   = (const float*)d_in[9];
    const float* traj_w = (const float*)d_in[10];
    const float* traj_b = (const float*)d_in[11];
    const float* offs_w = (const float*)d_in[12];
    const float* offs_b = (const float*)d_in[13];
    const float* attw_w = (const float*)d_in[14];
    const float* attw_b = (const float*)d_in[15];
    const float* out_w  = (const float*)d_in[16];
    const float* out_b  = (const float*)d_in[17];
    float* out = (float*)d_out;

    float *p_tf, *p_kv, *p_q, *p_ctx, *p_oa, *p_wc, *p_bc;
    cudaGetSymbolAddress((void**)&p_tf,  g_tf);
    cudaGetSymbolAddress((void**)&p_kv,  g_kv);
    cudaGetSymbolAddress((void**)&p_q,   g_q);
    cudaGetSymbolAddress((void**)&p_ctx, g_ctx);
    cudaGetSymbolAddress((void**)&p_oa,  g_oa);
    cudaGetSymbolAddress((void**)&p_wc,  g_wc);
    cudaGetSymbolAddress((void**)&p_bc,  g_bc);

    cudaFuncSetAttribute(k_attn,    cudaFuncAttributeMaxDynamicSharedMemorySize, 65536);
    cudaFuncSetAttribute(gemm_mma3, cudaFuncAttributeMaxDynamicSharedMemorySize, 51200);

    // (0) trajectory proj + weight concat
    k_prep<<<Bsz * NT + 97, 256>>>(trajp, traj_w, traj_b, offs_w, offs_b, attw_w, attw_b);
    // (1) fused k+v projection (fp32 scalar — feeds high-amplification path)
    gemm_bias<<<dim3(8, 16), 256>>>(p_tf, in_w + 256 * 256, in_b + 256, p_kv, 512);
    // (2) q projection (3xTF32, fp32-grade)
    gemm_mma3<<<dim3(4, 256), 256, 51200>>>(query, in_w, in_b, p_q, 256);
    // (3) attention (two-tile, 64KB smem)
    k_attn<<<1024, 256, 65536>>>();
    // (4) mha out projection (3xTF32)
    gemm_mma3<<<dim3(4, 256), 256, 51200>>>(p_ctx, mha_w, mha_b, p_q, 256);
    // (5) residual + LN (g_q + query -> g_ctx)
    k_ln<<<Bsz * NG, 256>>>(query, ln_g, ln_b);
    // (6) offs + attw fused GEMM (3xTF32), N=96
    gemm_mma3<<<dim3(2, 256), 256, 51200>>>(p_ctx, p_wc, p_bc, p_oa, 96);
    // (7) value transpose to fp16 (B,H,W,C)
    k_transpose<<<dim3(32, 128, 4), dim3(32, 8)>>>(value);
    // (8) deformable sampling (writes scrambled S into g_q)
    k_sample<<<2048, 128>>>(refp);
    // (9) final projection via single-pass tf32 mma
    gemm_mma<<<dim3(4, 256), 256>>>(p_q, out_w, out_b, out);
}

// round 10
// speedup vs baseline: 2.5420x; 2.5420x over previous
#include <cuda_runtime.h>
#include <cuda_fp16.h>
#include <math.h>
#include <stdint.h>

#define Bsz 4
#define NG  8192
#define Cdim 256
#define Hh  128
#define Ww  128
#define NT  512
#define EPSLN 1e-5f
#define ATTN_SCALE 0.17677669529663687f

__device__ float  g_q  [Bsz*NG*Cdim];            // sampled S buffer
__device__ float  g_ctx[Bsz*NG*Cdim];            // fused ctx+LN output
__device__ __half g_vt [(size_t)Bsz*Hh*Ww*Cdim]; // value transposed (B,H,W,C), fp16
__device__ float  g_oa [Bsz*NG*96];
__device__ float  g_wc [96*Cdim];
__device__ float  g_bc [96];
// rank-3 attention precomputes
__device__ float  g_kv6[6*256];                  // Kx Ky K1 Vx Vy V1
__device__ float  g_A  [24*256];                 // coef weights (e = m*3+{x,y,1})
__device__ float  g_Ab [24];
__device__ float  g_Mw [16*256];                 // ctx->mha weights (e = m*2+{x,y})
__device__ float  g_Mc [256];                    // const vector (V1 path + mha_b)
__device__ float  g_coef[(size_t)Bsz*NG*24];
__device__ float  g_R  [(size_t)Bsz*NG*16];

// ---- weight concat (offs|attw) ----
__global__ __launch_bounds__(256) void k_prep(const float* __restrict__ ow,
                                              const float* __restrict__ ob,
                                              const float* __restrict__ aw,
                                              const float* __restrict__ ab) {
    int i = blockIdx.x * 256 + threadIdx.x;
    if (i < 64 * 256)                 g_wc[i] = ow[i];
    else if (i < 96 * 256)            g_wc[i] = aw[i - 64 * 256];
    else if (i < 96 * 256 + 64)       g_bc[i - 96 * 256] = ob[i - 96 * 256];
    else if (i < 96 * 256 + 96)       g_bc[i - 96 * 256] = ab[i - 96 * 256 - 64];
}

// ---- rank-3 K/V basis: Kx,Ky,K1,Vx,Vy,V1 (256 each) ----
__global__ __launch_bounds__(256) void k_precomp(const float* __restrict__ in_w,
                                                 const float* __restrict__ in_b,
                                                 const float* __restrict__ tw,
                                                 const float* __restrict__ tb) {
    int c = threadIdx.x;
    const float* wk = in_w + (size_t)(256 + c) * 256;
    const float* wv = in_w + (size_t)(512 + c) * 256;
    float kx = 0.f, ky = 0.f, k1 = 0.f, vx = 0.f, vy = 0.f, v1 = 0.f;
    for (int j = 0; j < 256; j++) {
        float a = wk[j], bnn = wv[j];
        float tx = tw[j * 2], ty = tw[j * 2 + 1], tbj = tb[j];
        kx = fmaf(a, tx, kx); ky = fmaf(a, ty, ky); k1 = fmaf(a, tbj, k1);
        vx = fmaf(bnn, tx, vx); vy = fmaf(bnn, ty, vy); v1 = fmaf(bnn, tbj, v1);
    }
    g_kv6[0 * 256 + c] = kx;
    g_kv6[1 * 256 + c] = ky;
    g_kv6[2 * 256 + c] = k1 + in_b[256 + c];
    g_kv6[3 * 256 + c] = vx;
    g_kv6[4 * 256 + c] = vy;
    g_kv6[5 * 256 + c] = v1 + in_b[512 + c];
}

// ---- fold q-proj into coef weights A, and mha-out into Mw/Mc ----
__global__ __launch_bounds__(256) void k_precomp2(const float* __restrict__ in_w,
                                                  const float* __restrict__ in_b,
                                                  const float* __restrict__ mw,
                                                  const float* __restrict__ mb) {
    int bi = blockIdx.x, t = threadIdx.x;
    if (bi < 24) {                       // A[e][j] = sum_c wq[m*32+c][j] * KC[comp][m*32+c]
        int m = bi / 3, comp = bi % 3;
        const float* KC = g_kv6 + comp * 256 + m * 32;
        float a = 0.f;
#pragma unroll 8
        for (int c = 0; c < 32; c++)
            a = fmaf(in_w[(size_t)(m * 32 + c) * 256 + t], KC[c], a);
        g_A[bi * 256 + t] = a * ATTN_SCALE;
        if (t < 32) {
            float v = in_b[m * 32 + t] * KC[t];
#pragma unroll
            for (int o = 16; o; o >>= 1) v += __shfl_xor_sync(0xffffffffu, v, o);
            if (t == 0) g_Ab[bi] = v * ATTN_SCALE;
        }
    } else if (bi < 40) {                // Mw[e2][o] = sum_c mha_w[o][m*32+c] * VC[comp][m*32+c]
        int e2 = bi - 24, m = e2 >> 1, comp = e2 & 1;
        const float* VC = g_kv6 + (3 + comp) * 256 + m * 32;
        const float* mwr = mw + (size_t)t * 256 + m * 32;
        float a = 0.f;
#pragma unroll 8
        for (int c = 0; c < 32; c++) a = fmaf(mwr[c], VC[c], a);
        g_Mw[e2 * 256 + t] = a;
    } else {                             // Mc[o] = sum_c mha_w[o][c]*V1[c] + mha_b[o]
        const float* V1 = g_kv6 + 5 * 256;
        const float* mwr = mw + (size_t)t * 256;
        float a = mb[t];
        for (int c = 0; c < 256; c++) a = fmaf(mwr[c], V1[c], a);
        g_Mc[t] = a;
    }
}

// ---- scalar fp32 GEMM: Y[R x N] = X[R x 256] @ W[N x 256]^T + bias ----
__global__ __launch_bounds__(256) void gemm_bias(const float* __restrict__ X,
                                                 const float* __restrict__ W,
                                                 const float* __restrict__ bias,
                                                 float* __restrict__ Y, int N) {
    __shared__ __align__(16) float As[16][132];
    __shared__ __align__(16) float Bs[16][68];
    int tid = threadIdx.x;
    int row0 = blockIdx.y * 128, n0 = blockIdx.x * 64;
    int rg = tid >> 4, cg = tid & 15;
    float acc[8][4];
#pragma unroll
    for (int i = 0; i < 8; i++)
#pragma unroll
        for (int j = 0; j < 4; j++) acc[i][j] = 0.f;

    int ar = tid >> 1, akq = (tid & 1) * 8;
    int bn = tid >> 2, bkq = (tid & 3) * 4;
    bool bvalid = (n0 + bn) < N;
    const float* Xp = X + (size_t)(row0 + ar) * 256 + akq;
    const float* Wp = W + (size_t)(bvalid ? (n0 + bn) : 0) * 256 + bkq;

    for (int kt = 0; kt < 16; kt++) {
        int k0 = kt * 16;
        float4 a0 = *(const float4*)(Xp + k0);
        float4 a1 = *(const float4*)(Xp + k0 + 4);
        float4 b0 = bvalid ? *(const float4*)(Wp + k0) : make_float4(0.f, 0.f, 0.f, 0.f);
        As[akq + 0][ar] = a0.x; As[akq + 1][ar] = a0.y;
        As[akq + 2][ar] = a0.z; As[akq + 3][ar] = a0.w;
        As[akq + 4][ar] = a1.x; As[akq + 5][ar] = a1.y;
        As[akq + 6][ar] = a1.z; As[akq + 7][ar] = a1.w;
        Bs[bkq + 0][bn] = b0.x; Bs[bkq + 1][bn] = b0.y;
        Bs[bkq + 2][bn] = b0.z; Bs[bkq + 3][bn] = b0.w;
        __syncthreads();
#pragma unroll
        for (int kk = 0; kk < 16; kk++) {
            float4 av0 = *(const float4*)&As[kk][rg * 8];
            float4 av1 = *(const float4*)&As[kk][rg * 8 + 4];
            float4 bv  = *(const float4*)&Bs[kk][cg * 4];
            float a[8] = {av0.x, av0.y, av0.z, av0.w, av1.x, av1.y, av1.z, av1.w};
            float bb[4] = {bv.x, bv.y, bv.z, bv.w};
#pragma unroll
            for (int i = 0; i < 8; i++)
#pragma unroll
                for (int j = 0; j < 4; j++) acc[i][j] = fmaf(a[i], bb[j], acc[i][j]);
        }
        __syncthreads();
    }
    int nc = n0 + cg * 4;
    if (nc < N) {
        float4 bb = *(const float4*)(bias + nc);
#pragma unroll
        for (int i = 0; i < 8; i++) {
            float4 o;
            o.x = acc[i][0] + bb.x; o.y = acc[i][1] + bb.y;
            o.z = acc[i][2] + bb.z; o.w = acc[i][3] + bb.w;
            *(float4*)(Y + (size_t)(row0 + rg * 8 + i) * N + nc) = o;
        }
    }
}

// ---- rank-3 attention: thread = (query, head); keys from smem; outputs rx,ry ----
__global__ __launch_bounds__(256) void k_attn3(const float* __restrict__ tp) {
    __shared__ float sxy[NT * 2];
    int bi = blockIdx.x;                  // 1024 = B * 256
    int b = bi >> 8, qt = bi & 255;
    int tid = threadIdx.x;
    for (int t = tid; t < NT; t += 256) {
        float2 v = ((const float2*)tp)[b * NT + t];
        sxy[t * 2] = v.x; sxy[t * 2 + 1] = v.y;
    }
    __syncthreads();

    int m = tid & 7;
    int g = qt * 32 + (tid >> 3);
    size_t gi = (size_t)b * NG + g;
    const float* cf = g_coef + gi * 24 + m * 3;
    float al = cf[0], be = cf[1], ga = cf[2];
    float Sp = 0.f, Sx = 0.f, Sy = 0.f;
#pragma unroll 4
    for (int t = 0; t < NT; t++) {
        float2 xy = ((const float2*)sxy)[t];
        float s = fmaf(al, xy.x, fmaf(be, xy.y, ga));
        float p = __expf(s);
        Sp += p;
        Sx = fmaf(p, xy.x, Sx);
        Sy = fmaf(p, xy.y, Sy);
    }
    float inv = 1.f / Sp;
    float2 r = {Sx * inv, Sy * inv};
    ((float2*)(g_R + gi * 16))[m] = r;
}

// ---- fused mha-out (K=16) + residual + LayerNorm -> g_ctx ----
__global__ __launch_bounds__(256) void k_ctxln(const float* __restrict__ q_in,
                                               const float* __restrict__ lng,
                                               const float* __restrict__ lnb) {
    __shared__ float sMw[16][256];
    __shared__ float sR[8][16];
    __shared__ float sMc[256];
    __shared__ float red[8][8];
    int tid = threadIdx.x;
    int r0 = blockIdx.x * 8;
#pragma unroll
    for (int k = 0; k < 16; k++) sMw[k][tid] = g_Mw[k * 256 + tid];
    sMc[tid] = g_Mc[tid];
    if (tid < 128) {
        int r = tid >> 4, k = tid & 15;
        sR[r][k] = g_R[(size_t)(r0 + r) * 16 + k];
    }
    __syncthreads();

    float xv[8];
#pragma unroll
    for (int r = 0; r < 8; r++) {
        float acc = sMc[tid];
#pragma unroll
        for (int k = 0; k < 16; k++) acc = fmaf(sR[r][k], sMw[k][tid], acc);
        xv[r] = acc + q_in[(size_t)(r0 + r) * 256 + tid];
    }
    int lane = tid & 31, w = tid >> 5;
    // mean
#pragma unroll
    for (int r = 0; r < 8; r++) {
        float s = xv[r];
#pragma unroll
        for (int o = 16; o; o >>= 1) s += __shfl_xor_sync(0xffffffffu, s, o);
        if (!lane) red[w][r] = s;
    }
    __syncthreads();
    float mu[8];
#pragma unroll
    for (int r = 0; r < 8; r++) {
        float tot = 0.f;
#pragma unroll
        for (int i = 0; i < 8; i++) tot += red[i][r];
        mu[r] = tot * (1.f / 256.f);
    }
    __syncthreads();
    // var
#pragma unroll
    for (int r = 0; r < 8; r++) {
        float d = xv[r] - mu[r];
        float s = d * d;
#pragma unroll
        for (int o = 16; o; o >>= 1) s += __shfl_xor_sync(0xffffffffu, s, o);
        if (!lane) red[w][r] = s;
    }
    __syncthreads();
    float gg = lng[tid], bb = lnb[tid];
#pragma unroll
    for (int r = 0; r < 8; r++) {
        float tot = 0.f;
#pragma unroll
        for (int i = 0; i < 8; i++) tot += red[i][r];
        float inv = rsqrtf(tot * (1.f / 256.f) + EPSLN);
        g_ctx[(size_t)(r0 + r) * 256 + tid] = (xv[r] - mu[r]) * inv * gg + bb;
    }
}

// ---- single-pass tf32 mma GEMM (final projection, 1x error path), N=256 fixed ----
__device__ __forceinline__ uint32_t f2tf32(float x) {
    uint32_t r; asm("cvt.rna.tf32.f32 %0, %1;" : "=r"(r) : "f"(x)); return r;
}
#define MMA_TF32(acc, a0, a1, a2, a3, b0, b1) \
    asm volatile("mma.sync.aligned.m16n8k8.row.col.f32.tf32.tf32.f32 " \
        "{%0,%1,%2,%3}, {%4,%5,%6,%7}, {%8,%9}, {%0,%1,%2,%3};" \
        : "+f"((acc)[0]), "+f"((acc)[1]), "+f"((acc)[2]), "+f"((acc)[3]) \
        : "r"(a0), "r"(a1), "r"(a2), "r"(a3), "r"(b0), "r"(b1))

__global__ __launch_bounds__(256) void gemm_mma(const float* __restrict__ X,
                                                const float* __restrict__ W,
                                                const float* __restrict__ bias,
                                                float* __restrict__ Y) {
    __shared__ uint32_t As[32][132];
    __shared__ uint32_t Bs[32][68];
    int tid = threadIdx.x;
    int row0 = blockIdx.y * 128, n0b = blockIdx.x * 64;
    int w = tid >> 5, lane = tid & 31, grp = lane >> 2, qid = lane & 3;
    float acc[8][4];
#pragma unroll
    for (int j = 0; j < 8; j++)
#pragma unroll
        for (int i = 0; i < 4; i++) acc[j][i] = 0.f;

    int ar = tid >> 1, ak = (tid & 1) * 16;
    int br = tid >> 2, bk = (tid & 3) * 8;
    const float* Xp = X + (size_t)(row0 + ar) * 256 + ak;
    const float* Wp = W + (size_t)(n0b + br) * 256 + bk;

    for (int kt = 0; kt < 8; kt++) {
        int k0 = kt * 32;
#pragma unroll
        for (int i = 0; i < 4; i++) {
            float4 v = *(const float4*)(Xp + k0 + i * 4);
            As[ak + i * 4 + 0][ar] = f2tf32(v.x); As[ak + i * 4 + 1][ar] = f2tf32(v.y);
            As[ak + i * 4 + 2][ar] = f2tf32(v.z); As[ak + i * 4 + 3][ar] = f2tf32(v.w);
        }
#pragma unroll
        for (int i = 0; i < 2; i++) {
            float4 v = *(const float4*)(Wp + k0 + i * 4);
            Bs[bk + i * 4 + 0][br] = f2tf32(v.x); Bs[bk + i * 4 + 1][br] = f2tf32(v.y);
            Bs[bk + i * 4 + 2][br] = f2tf32(v.z); Bs[bk + i * 4 + 3][br] = f2tf32(v.w);
        }
        __syncthreads();
#pragma unroll
        for (int kk = 0; kk < 4; kk++) {
            int kb = kk * 8;
            uint32_t a0 = As[kb + qid][w * 16 + grp];
            uint32_t a1 = As[kb + qid][w * 16 + grp + 8];
            uint32_t a2 = As[kb + qid + 4][w * 16 + grp];
            uint32_t a3 = As[kb + qid + 4][w * 16 + grp + 8];
#pragma unroll
            for (int j = 0; j < 8; j++) {
                uint32_t b0 = Bs[kb + qid][j * 8 + grp];
                uint32_t b1 = Bs[kb + qid + 4][j * 8 + grp];
                MMA_TF32(acc[j], a0, a1, a2, a3, b0, b1);
            }
        }
        __syncthreads();
    }
    int r = row0 + w * 16 + grp;
#pragma unroll
    for (int j = 0; j < 8; j++) {
        int c = n0b + j * 8 + qid * 2;
        float2 bb = *(const float2*)(bias + c);
        float2 o0 = {acc[j][0] + bb.x, acc[j][1] + bb.y};
        float2 o1 = {acc[j][2] + bb.x, acc[j][3] + bb.y};
        *(float2*)(Y + (size_t)r * 256 + c) = o0;
        *(float2*)(Y + (size_t)(r + 8) * 256 + c) = o1;
    }
}

// ---- value (B,C,H,W) fp32 -> (B,H,W,C) fp16 ----
__global__ __launch_bounds__(256) void k_transpose(const float* __restrict__ val) {
    __shared__ float tile[32][33];
    int tx = threadIdx.x, ty = threadIdx.y;
    int b = blockIdx.z, y = blockIdx.y;
    int c0 = (blockIdx.x >> 2) * 32, x0 = (blockIdx.x & 3) * 32;
#pragma unroll
    for (int i = 0; i < 4; i++)
        tile[ty + i * 8][tx] = val[(((size_t)(b * Cdim + c0 + ty + i * 8) * Hh + y) * Ww) + x0 + tx];
    __syncthreads();
#pragma unroll
    for (int i = 0; i < 4; i++)
        g_vt[(((size_t)(b * Hh + y) * Ww + x0 + ty + i * 8) * Cdim) + c0 + tx] =
            __float2half(tile[tx][ty + i * 8]);
}

// ---- bilinear corner accumulate (fp16 values, fp32 math) ----
__device__ __forceinline__ void corner(const __half* __restrict__ vb, int x, int y,
                                       int moff, float w, float* acc) {
    if (x < 0 || x >= Ww || y < 0 || y >= Hh) return;
    const uint4* p = (const uint4*)(vb + ((size_t)(y * Ww + x)) * Cdim + moff);
#pragma unroll
    for (int i = 0; i < 4; i++) {
        uint4 u = p[i];
        const __half2* h = (const __half2*)&u;
#pragma unroll
        for (int j = 0; j < 4; j++) {
            float2 f = __half22float2(h[j]);
            acc[i * 8 + j * 2]     = fmaf(w, f.x, acc[i * 8 + j * 2]);
            acc[i * 8 + j * 2 + 1] = fmaf(w, f.y, acc[i * 8 + j * 2 + 1]);
        }
    }
}

// ---- deformable sampling: thread = (query, m); scrambled store into g_q ----
__global__ __launch_bounds__(128) void k_sample(const float* __restrict__ refp) {
    int bi = blockIdx.x;            // 2048 = B * 8 * 64
    int tid = threadIdx.x;
    int b = bi >> 9;
    int m = (bi >> 6) & 7;
    int gg = (bi & 63) * 128 + tid;
    int gh = gg >> 8, gl = gg & 255;
    size_t qidx = (size_t)b * NG + gg;
    float rx = refp[qidx * 2], ry = refp[qidx * 2 + 1];
    const float* oar = g_oa + qidx * 96;

    float a0 = oar[64 + m * 4], a1 = oar[64 + m * 4 + 1];
    float a2 = oar[64 + m * 4 + 2], a3 = oar[64 + m * 4 + 3];
    float amx = fmaxf(fmaxf(a0, a1), fmaxf(a2, a3));
    float e0 = __expf(a0 - amx), e1 = __expf(a1 - amx);
    float e2 = __expf(a2 - amx), e3 = __expf(a3 - amx);
    float inv = 1.f / (e0 + e1 + e2 + e3);
    float aw[4] = {e0 * inv, e1 * inv, e2 * inv, e3 * inv};

    const __half* vb = g_vt + (size_t)b * Hh * Ww * Cdim;
    float acc[32];
#pragma unroll
    for (int i = 0; i < 32; i++) acc[i] = 0.f;

#pragma unroll
    for (int p = 0; p < 4; p++) {
        float gx = (rx + oar[m * 8 + p * 2]) * (float)Ww - 0.5f;
        float gy = (ry + oar[m * 8 + p * 2 + 1]) * (float)Hh - 0.5f;
        float x0f = floorf(gx), y0f = floorf(gy);
        float fx = gx - x0f, fy = gy - y0f;
        int x0 = (int)x0f, y0 = (int)y0f;
        float w = aw[p];
        corner(vb, x0,     y0,     m * 32, (1.f - fx) * (1.f - fy) * w, acc);
        corner(vb, x0 + 1, y0,     m * 32, fx * (1.f - fy) * w, acc);
        corner(vb, x0,     y0 + 1, m * 32, (1.f - fx) * fy * w, acc);
        corner(vb, x0 + 1, y0 + 1, m * 32, fx * fy * w, acc);
    }
    // S[b][ch*256 + m*32 + gh][gl]
    float* S = g_q + (size_t)b * NG * 256 + (size_t)(m * 32 + gh) * 256 + gl;
#pragma unroll
    for (int ch = 0; ch < 32; ch++) S[(size_t)ch * 65536] = acc[ch];
}

extern "C" void kernel_launch(void* const* d_in, const int* in_sizes, int n_in,
                              void* d_out, int out_size) {
    const float* query  = (const float*)d_in[0];
    const float* value  = (const float*)d_in[1];
    const float* refp   = (const float*)d_in[2];
    const float* trajp  = (const float*)d_in[3];
    const float* in_w   = (const float*)d_in[4];
    const float* in_b   = (const float*)d_in[5];
    const float* mha_w  = (const float*)d_in[6];
    const float* mha_b  = (const float*)d_in[7];
    const float* ln_g   = (const float*)d_in[8];
    const float* ln_b   = (const float*)d_in[9];
    const float* offs_w = (const float*)d_in[12];
    const float* offs_b = (const float*)d_in[13];
    const float* attw_w = (const float*)d_in[14];
    const float* attw_b = (const float*)d_in[15];
    const float* out_w  = (const float*)d_in[16];
    const float* out_b  = (const float*)d_in[17];
    float* out = (float*)d_out;

    float *p_q, *p_ctx, *p_oa, *p_wc, *p_bc, *p_A, *p_Ab, *p_coef;
    cudaGetSymbolAddress((void**)&p_q,    g_q);
    cudaGetSymbolAddress((void**)&p_ctx,  g_ctx);
    cudaGetSymbolAddress((void**)&p_oa,   g_oa);
    cudaGetSymbolAddress((void**)&p_wc,   g_wc);
    cudaGetSymbolAddress((void**)&p_bc,   g_bc);
    cudaGetSymbolAddress((void**)&p_A,    g_A);
    cudaGetSymbolAddress((void**)&p_Ab,   g_Ab);
    cudaGetSymbolAddress((void**)&p_coef, g_coef);

    // (0) weight concat + rank-3 precomputes
    k_prep<<<97, 256>>>(offs_w, offs_b, attw_w, attw_b);
    k_precomp<<<1, 256>>>(in_w, in_b, d_in[10] ? (const float*)d_in[10] : nullptr,
                          (const float*)d_in[11]);
    k_precomp2<<<41, 256>>>(in_w, in_b, mha_w, mha_b);
    // (1) coef GEMM: coef[g,24] = query @ A^T + Ab
    gemm_bias<<<dim3(1, 256), 256>>>(query, p_A, p_Ab, p_coef, 24);
    // (2) rank-3 attention -> g_R
    k_attn3<<<1024, 256>>>(trajp);
    // (3) fused mha-out(K=16) + residual + LN -> g_ctx
    k_ctxln<<<4096, 256>>>(query, ln_g, ln_b);
    // (4) offs + attw fused GEMM (scalar), N=96
    gemm_bias<<<dim3(2, 256), 256>>>(p_ctx, p_wc, p_bc, p_oa, 96);
    // (5) value transpose to fp16 (B,H,W,C)
    k_transpose<<<dim3(32, 128, 4), dim3(32, 8)>>>(value);
    // (6) deformable sampling (writes scrambled S into g_q)
    k_sample<<<2048, 128>>>(refp);
    // (7) final projection via single-pass tf32 mma
    gemm_mma<<<dim3(4, 256), 256>>>(p_q, out_w, out_b, out);
}

// round 11
// speedup vs baseline: 2.8742x; 1.1307x over previous
#include <cuda_runtime.h>
#include <cuda_fp16.h>
#include <math.h>
#include <stdint.h>

#define Bsz 4
#define NG  8192
#define Cdim 256
#define Hh  128
#define Ww  128
#define NT  512
#define EPSLN 1e-5f
#define ATTN_SCALE 0.17677669529663687f

__device__ __half g_S  [(size_t)Bsz*NG*Cdim];     // sampled S (fp16, 1x path)
__device__ float  g_ctx[Bsz*NG*Cdim];             // fused ctx+LN output
__device__ __half g_vt [(size_t)Bsz*Hh*Ww*Cdim];  // value transposed (B,H,W,C), fp16
__device__ float  g_oa [Bsz*NG*96];
__device__ float  g_wc [96*Cdim];
__device__ float  g_bc [96];
// rank-3 attention precomputes (gamma dropped: cancels in softmax ratio)
__device__ float  g_kv6[6*256];                   // Kx Ky K1 Vx Vy V1
__device__ float  g_A  [16*256];                  // coef weights (e = m*2+{x,y})
__device__ float  g_Ab [16];
__device__ float  g_Mw [16*256];                  // ctx->mha weights (e = m*2+{x,y})
__device__ float  g_Mc [256];                     // const vector (V1 path + mha_b)
__device__ float  g_coef[(size_t)Bsz*NG*16];
__device__ float  g_R  [(size_t)Bsz*NG*16];

// ---- weight concat (offs|attw) ----
__global__ __launch_bounds__(256) void k_prep(const float* __restrict__ ow,
                                              const float* __restrict__ ob,
                                              const float* __restrict__ aw,
                                              const float* __restrict__ ab) {
    int i = blockIdx.x * 256 + threadIdx.x;
    if (i < 64 * 256)                 g_wc[i] = ow[i];
    else if (i < 96 * 256)            g_wc[i] = aw[i - 64 * 256];
    else if (i < 96 * 256 + 64)       g_bc[i - 96 * 256] = ob[i - 96 * 256];
    else if (i < 96 * 256 + 96)       g_bc[i - 96 * 256] = ab[i - 96 * 256 - 64];
}

// ---- rank-3 K/V basis: Kx,Ky,K1,Vx,Vy,V1 (256 each) ----
__global__ __launch_bounds__(256) void k_precomp(const float* __restrict__ in_w,
                                                 const float* __restrict__ in_b,
                                                 const float* __restrict__ tw,
                                                 const float* __restrict__ tb) {
    int c = threadIdx.x;
    const float* wk = in_w + (size_t)(256 + c) * 256;
    const float* wv = in_w + (size_t)(512 + c) * 256;
    float kx = 0.f, ky = 0.f, k1 = 0.f, vx = 0.f, vy = 0.f, v1 = 0.f;
    for (int j = 0; j < 256; j++) {
        float a = wk[j], bnn = wv[j];
        float tx = tw[j * 2], ty = tw[j * 2 + 1], tbj = tb[j];
        kx = fmaf(a, tx, kx); ky = fmaf(a, ty, ky); k1 = fmaf(a, tbj, k1);
        vx = fmaf(bnn, tx, vx); vy = fmaf(bnn, ty, vy); v1 = fmaf(bnn, tbj, v1);
    }
    g_kv6[0 * 256 + c] = kx;
    g_kv6[1 * 256 + c] = ky;
    g_kv6[2 * 256 + c] = k1 + in_b[256 + c];
    g_kv6[3 * 256 + c] = vx;
    g_kv6[4 * 256 + c] = vy;
    g_kv6[5 * 256 + c] = v1 + in_b[512 + c];
}

// ---- fold q-proj into coef weights A (x,y only), mha-out into Mw/Mc ----
__global__ __launch_bounds__(256) void k_precomp2(const float* __restrict__ in_w,
                                                  const float* __restrict__ in_b,
                                                  const float* __restrict__ mw,
                                                  const float* __restrict__ mb) {
    int bi = blockIdx.x, t = threadIdx.x;
    if (bi < 16) {                       // A[e][j] = sum_c wq[m*32+c][j] * KC[comp][m*32+c]
        int m = bi >> 1, comp = bi & 1;
        const float* KC = g_kv6 + comp * 256 + m * 32;
        float a = 0.f;
#pragma unroll 8
        for (int c = 0; c < 32; c++)
            a = fmaf(in_w[(size_t)(m * 32 + c) * 256 + t], KC[c], a);
        g_A[bi * 256 + t] = a * ATTN_SCALE;
        if (t < 32) {
            float v = in_b[m * 32 + t] * KC[t];
#pragma unroll
            for (int o = 16; o; o >>= 1) v += __shfl_xor_sync(0xffffffffu, v, o);
            if (t == 0) g_Ab[bi] = v * ATTN_SCALE;
        }
    } else if (bi < 32) {                // Mw[e2][o] = sum_c mha_w[o][m*32+c] * VC[comp][..]
        int e2 = bi - 16, m = e2 >> 1, comp = e2 & 1;
        const float* VC = g_kv6 + (3 + comp) * 256 + m * 32;
        const float* mwr = mw + (size_t)t * 256 + m * 32;
        float a = 0.f;
#pragma unroll 8
        for (int c = 0; c < 32; c++) a = fmaf(mwr[c], VC[c], a);
        g_Mw[e2 * 256 + t] = a;
    } else {                             // Mc[o] = sum_c mha_w[o][c]*V1[c] + mha_b[o]
        const float* V1 = g_kv6 + 5 * 256;
        const float* mwr = mw + (size_t)t * 256;
        float a = mb[t];
        for (int c = 0; c < 256; c++) a = fmaf(mwr[c], V1[c], a);
        g_Mc[t] = a;
    }
}

// ---- thin coef GEMM: coef[32768][16] = query @ A^T + Ab ; 2 threads/row ----
__global__ __launch_bounds__(128) void k_coef(const float* __restrict__ q) {
    __shared__ float sA[256][17];   // sA[k][e], padded
    __shared__ float sAb[16];
    int tid = threadIdx.x;
    for (int i = tid; i < 4096; i += 128) {
        int e = i >> 8, k = i & 255;
        sA[k][e] = g_A[i];
    }
    if (tid < 16) sAb[tid] = g_Ab[tid];
    __syncthreads();
    int row = blockIdx.x * 64 + (tid >> 1);
    int h = tid & 1;
    const float4* qp = (const float4*)(q + (size_t)row * 256 + h * 128);
    float acc[16];
#pragma unroll
    for (int e = 0; e < 16; e++) acc[e] = 0.f;
#pragma unroll 8
    for (int i = 0; i < 32; i++) {
        float4 v = qp[i];
        int k = h * 128 + i * 4;
#pragma unroll
        for (int e = 0; e < 16; e++) {
            acc[e] = fmaf(v.x, sA[k][e],     acc[e]);
            acc[e] = fmaf(v.y, sA[k + 1][e], acc[e]);
            acc[e] = fmaf(v.z, sA[k + 2][e], acc[e]);
            acc[e] = fmaf(v.w, sA[k + 3][e], acc[e]);
        }
    }
#pragma unroll
    for (int e = 0; e < 16; e++)
        acc[e] += __shfl_xor_sync(0xffffffffu, acc[e], 1);
    float* dst = g_coef + (size_t)row * 16 + h * 8;
#pragma unroll
    for (int e = 0; e < 8; e++) dst[e] = acc[h * 8 + e] + sAb[h * 8 + e];
}

// ---- rank-3 attention: thread = (query, head); gamma-free scores ----
__global__ __launch_bounds__(256) void k_attn3(const float* __restrict__ tp) {
    __shared__ float sxy[NT * 2];
    int bi = blockIdx.x;                  // 1024 = B * 256
    int b = bi >> 8, qt = bi & 255;
    int tid = threadIdx.x;
    for (int t = tid; t < NT; t += 256) {
        float2 v = ((const float2*)tp)[b * NT + t];
        sxy[t * 2] = v.x; sxy[t * 2 + 1] = v.y;
    }
    __syncthreads();

    int m = tid & 7;
    int g = qt * 32 + (tid >> 3);
    size_t gi = (size_t)b * NG + g;
    const float* cf = g_coef + gi * 16 + m * 2;
    float al = cf[0], be = cf[1];
    float Sp = 0.f, Sx = 0.f, Sy = 0.f;
#pragma unroll 4
    for (int t = 0; t < NT; t++) {
        float2 xy = ((const float2*)sxy)[t];
        float s = fmaf(al, xy.x, be * xy.y);
        float p = __expf(s);
        Sp += p;
        Sx = fmaf(p, xy.x, Sx);
        Sy = fmaf(p, xy.y, Sy);
    }
    float inv = 1.f / Sp;
    float2 r = {Sx * inv, Sy * inv};
    ((float2*)(g_R + gi * 16))[m] = r;
}

// ---- fused mha-out (K=16) + residual + LayerNorm -> g_ctx ----
__global__ __launch_bounds__(256) void k_ctxln(const float* __restrict__ q_in,
                                               const float* __restrict__ lng,
                                               const float* __restrict__ lnb) {
    __shared__ float sMw[16][256];
    __shared__ float sR[8][16];
    __shared__ float sMc[256];
    __shared__ float red[8][8];
    int tid = threadIdx.x;
    int r0 = blockIdx.x * 8;
#pragma unroll
    for (int k = 0; k < 16; k++) sMw[k][tid] = g_Mw[k * 256 + tid];
    sMc[tid] = g_Mc[tid];
    if (tid < 128) {
        int r = tid >> 4, k = tid & 15;
        sR[r][k] = g_R[(size_t)(r0 + r) * 16 + k];
    }
    __syncthreads();

    float xv[8];
#pragma unroll
    for (int r = 0; r < 8; r++) {
        float acc = sMc[tid];
#pragma unroll
        for (int k = 0; k < 16; k++) acc = fmaf(sR[r][k], sMw[k][tid], acc);
        xv[r] = acc + q_in[(size_t)(r0 + r) * 256 + tid];
    }
    int lane = tid & 31, w = tid >> 5;
#pragma unroll
    for (int r = 0; r < 8; r++) {
        float s = xv[r];
#pragma unroll
        for (int o = 16; o; o >>= 1) s += __shfl_xor_sync(0xffffffffu, s, o);
        if (!lane) red[w][r] = s;
    }
    __syncthreads();
    float mu[8];
#pragma unroll
    for (int r = 0; r < 8; r++) {
        float tot = 0.f;
#pragma unroll
        for (int i = 0; i < 8; i++) tot += red[i][r];
        mu[r] = tot * (1.f / 256.f);
    }
    __syncthreads();
#pragma unroll
    for (int r = 0; r < 8; r++) {
        float d = xv[r] - mu[r];
        float s = d * d;
#pragma unroll
        for (int o = 16; o; o >>= 1) s += __shfl_xor_sync(0xffffffffu, s, o);
        if (!lane) red[w][r] = s;
    }
    __syncthreads();
    float gg = lng[tid], bb = lnb[tid];
#pragma unroll
    for (int r = 0; r < 8; r++) {
        float tot = 0.f;
#pragma unroll
        for (int i = 0; i < 8; i++) tot += red[i][r];
        float inv = rsqrtf(tot * (1.f / 256.f) + EPSLN);
        g_ctx[(size_t)(r0 + r) * 256 + tid] = (xv[r] - mu[r]) * inv * gg + bb;
    }
}

// ---- scalar fp32 GEMM (offs/attw: fp32-precision path) ----
__global__ __launch_bounds__(256) void gemm_bias(const float* __restrict__ X,
                                                 const float* __restrict__ W,
                                                 const float* __restrict__ bias,
                                                 float* __restrict__ Y, int N) {
    __shared__ __align__(16) float As[16][132];
    __shared__ __align__(16) float Bs[16][68];
    int tid = threadIdx.x;
    int row0 = blockIdx.y * 128, n0 = blockIdx.x * 64;
    int rg = tid >> 4, cg = tid & 15;
    float acc[8][4];
#pragma unroll
    for (int i = 0; i < 8; i++)
#pragma unroll
        for (int j = 0; j < 4; j++) acc[i][j] = 0.f;

    int ar = tid >> 1, akq = (tid & 1) * 8;
    int bn = tid >> 2, bkq = (tid & 3) * 4;
    bool bvalid = (n0 + bn) < N;
    const float* Xp = X + (size_t)(row0 + ar) * 256 + akq;
    const float* Wp = W + (size_t)(bvalid ? (n0 + bn) : 0) * 256 + bkq;

    for (int kt = 0; kt < 16; kt++) {
        int k0 = kt * 16;
        float4 a0 = *(const float4*)(Xp + k0);
        float4 a1 = *(const float4*)(Xp + k0 + 4);
        float4 b0 = bvalid ? *(const float4*)(Wp + k0) : make_float4(0.f, 0.f, 0.f, 0.f);
        As[akq + 0][ar] = a0.x; As[akq + 1][ar] = a0.y;
        As[akq + 2][ar] = a0.z; As[akq + 3][ar] = a0.w;
        As[akq + 4][ar] = a1.x; As[akq + 5][ar] = a1.y;
        As[akq + 6][ar] = a1.z; As[akq + 7][ar] = a1.w;
        Bs[bkq + 0][bn] = b0.x; Bs[bkq + 1][bn] = b0.y;
        Bs[bkq + 2][bn] = b0.z; Bs[bkq + 3][bn] = b0.w;
        __syncthreads();
#pragma unroll
        for (int kk = 0; kk < 16; kk++) {
            float4 av0 = *(const float4*)&As[kk][rg * 8];
            float4 av1 = *(const float4*)&As[kk][rg * 8 + 4];
            float4 bv  = *(const float4*)&Bs[kk][cg * 4];
            float a[8] = {av0.x, av0.y, av0.z, av0.w, av1.x, av1.y, av1.z, av1.w};
            float bb[4] = {bv.x, bv.y, bv.z, bv.w};
#pragma unroll
            for (int i = 0; i < 8; i++)
#pragma unroll
                for (int j = 0; j < 4; j++) acc[i][j] = fmaf(a[i], bb[j], acc[i][j]);
        }
        __syncthreads();
    }
    int nc = n0 + cg * 4;
    if (nc < N) {
        float4 bb = *(const float4*)(bias + nc);
#pragma unroll
        for (int i = 0; i < 8; i++) {
            float4 o;
            o.x = acc[i][0] + bb.x; o.y = acc[i][1] + bb.y;
            o.z = acc[i][2] + bb.z; o.w = acc[i][3] + bb.w;
            *(float4*)(Y + (size_t)(row0 + rg * 8 + i) * N + nc) = o;
        }
    }
}

// ---- fp16 HMMA final projection: Y[32768x256] = S(half) @ W^T + bias ----
__global__ __launch_bounds__(256) void gemm_hmma(const __half* __restrict__ X,
                                                 const float* __restrict__ W,
                                                 const float* __restrict__ bias,
                                                 float* __restrict__ Y) {
    __shared__ __half Ah[128][40];
    __shared__ __half Bh[64][40];
    int tid = threadIdx.x;
    int row0 = blockIdx.y * 128, n0b = blockIdx.x * 64;
    int w = tid >> 5, lane = tid & 31, grp = lane >> 2, qid = lane & 3;
    float acc[8][4];
#pragma unroll
    for (int j = 0; j < 8; j++)
#pragma unroll
        for (int i = 0; i < 4; i++) acc[j][i] = 0.f;

    int ar = tid >> 1, aseg = (tid & 1) * 16;     // X: row ar, halfs [aseg, aseg+16)
    int br = tid >> 2, bq = (tid & 3) * 8;        // W: row br, floats [bq, bq+8)
    const __half* Xp = X + (size_t)(row0 + ar) * 256 + aseg;
    const float* Wp = W + (size_t)(n0b + br) * 256 + bq;

    for (int kt = 0; kt < 8; kt++) {
        int k0t = kt * 32;
        {   // A tile: 128 rows x 32 halfs
            uint4 v0 = *(const uint4*)(Xp + k0t);
            uint4 v1 = *(const uint4*)(Xp + k0t + 8);
            *(uint4*)&Ah[ar][aseg] = v0;
            *(uint4*)&Ah[ar][aseg + 8] = v1;
        }
        {   // B tile: 64 rows x 32 floats -> halfs
            float4 v0 = *(const float4*)(Wp + k0t);
            float4 v1 = *(const float4*)(Wp + k0t + 4);
            __half2 h[4];
            h[0] = __floats2half2_rn(v0.x, v0.y); h[1] = __floats2half2_rn(v0.z, v0.w);
            h[2] = __floats2half2_rn(v1.x, v1.y); h[3] = __floats2half2_rn(v1.z, v1.w);
            *(uint4*)&Bh[br][bq] = *(uint4*)h;
        }
        __syncthreads();
#pragma unroll
        for (int ks = 0; ks < 2; ks++) {
            int k0 = ks * 16;
            uint32_t a0 = *(const uint32_t*)&Ah[w * 16 + grp][k0 + qid * 2];
            uint32_t a1 = *(const uint32_t*)&Ah[w * 16 + grp + 8][k0 + qid * 2];
            uint32_t a2 = *(const uint32_t*)&Ah[w * 16 + grp][k0 + qid * 2 + 8];
            uint32_t a3 = *(const uint32_t*)&Ah[w * 16 + grp + 8][k0 + qid * 2 + 8];
#pragma unroll
            for (int j = 0; j < 8; j++) {
                uint32_t b0 = *(const uint32_t*)&Bh[j * 8 + grp][k0 + qid * 2];
                uint32_t b1 = *(const uint32_t*)&Bh[j * 8 + grp][k0 + qid * 2 + 8];
                asm volatile(
                    "mma.sync.aligned.m16n8k16.row.col.f32.f16.f16.f32 "
                    "{%0,%1,%2,%3}, {%4,%5,%6,%7}, {%8,%9}, {%0,%1,%2,%3};"
                    : "+f"(acc[j][0]), "+f"(acc[j][1]), "+f"(acc[j][2]), "+f"(acc[j][3])
                    : "r"(a0), "r"(a1), "r"(a2), "r"(a3), "r"(b0), "r"(b1));
            }
        }
        __syncthreads();
    }
    int r = row0 + w * 16 + grp;
#pragma unroll
    for (int j = 0; j < 8; j++) {
        int c = n0b + j * 8 + qid * 2;
        float2 bb = *(const float2*)(bias + c);
        float2 o0 = {acc[j][0] + bb.x, acc[j][1] + bb.y};
        float2 o1 = {acc[j][2] + bb.x, acc[j][3] + bb.y};
        *(float2*)(Y + (size_t)r * 256 + c) = o0;
        *(float2*)(Y + (size_t)(r + 8) * 256 + c) = o1;
    }
}

// ---- value (B,C,H,W) fp32 -> (B,H,W,C) fp16 ----
__global__ __launch_bounds__(256) void k_transpose(const float* __restrict__ val) {
    __shared__ float tile[32][33];
    int tx = threadIdx.x, ty = threadIdx.y;
    int b = blockIdx.z, y = blockIdx.y;
    int c0 = (blockIdx.x >> 2) * 32, x0 = (blockIdx.x & 3) * 32;
#pragma unroll
    for (int i = 0; i < 4; i++)
        tile[ty + i * 8][tx] = val[(((size_t)(b * Cdim + c0 + ty + i * 8) * Hh + y) * Ww) + x0 + tx];
    __syncthreads();
#pragma unroll
    for (int i = 0; i < 4; i++)
        g_vt[(((size_t)(b * Hh + y) * Ww + x0 + ty + i * 8) * Cdim) + c0 + tx] =
            __float2half(tile[tx][ty + i * 8]);
}

// ---- bilinear corner accumulate (fp16 values, fp32 math) ----
__device__ __forceinline__ void corner(const __half* __restrict__ vb, int x, int y,
                                       int moff, float w, float* acc) {
    if (x < 0 || x >= Ww || y < 0 || y >= Hh) return;
    const uint4* p = (const uint4*)(vb + ((size_t)(y * Ww + x)) * Cdim + moff);
#pragma unroll
    for (int i = 0; i < 4; i++) {
        uint4 u = p[i];
        const __half2* h = (const __half2*)&u;
#pragma unroll
        for (int j = 0; j < 4; j++) {
            float2 f = __half22float2(h[j]);
            acc[i * 8 + j * 2]     = fmaf(w, f.x, acc[i * 8 + j * 2]);
            acc[i * 8 + j * 2 + 1] = fmaf(w, f.y, acc[i * 8 + j * 2 + 1]);
        }
    }
}

// ---- deformable sampling: thread = (query, m); scrambled fp16 store into g_S ----
__global__ __launch_bounds__(128) void k_sample(const float* __restrict__ refp) {
    int bi = blockIdx.x;            // 2048 = B * 8 * 64
    int tid = threadIdx.x;
    int b = bi >> 9;
    int m = (bi >> 6) & 7;
    int gg = (bi & 63) * 128 + tid;
    int gh = gg >> 8, gl = gg & 255;
    size_t qidx = (size_t)b * NG + gg;
    float rx = refp[qidx * 2], ry = refp[qidx * 2 + 1];
    const float* oar = g_oa + qidx * 96;

    float a0 = oar[64 + m * 4], a1 = oar[64 + m * 4 + 1];
    float a2 = oar[64 + m * 4 + 2], a3 = oar[64 + m * 4 + 3];
    float amx = fmaxf(fmaxf(a0, a1), fmaxf(a2, a3));
    float e0 = __expf(a0 - amx), e1 = __expf(a1 - amx);
    float e2 = __expf(a2 - amx), e3 = __expf(a3 - amx);
    float inv = 1.f / (e0 + e1 + e2 + e3);
    float aw[4] = {e0 * inv, e1 * inv, e2 * inv, e3 * inv};

    const __half* vb = g_vt + (size_t)b * Hh * Ww * Cdim;
    float acc[32];
#pragma unroll
    for (int i = 0; i < 32; i++) acc[i] = 0.f;

#pragma unroll
    for (int p = 0; p < 4; p++) {
        float gx = (rx + oar[m * 8 + p * 2]) * (float)Ww - 0.5f;
        float gy = (ry + oar[m * 8 + p * 2 + 1]) * (float)Hh - 0.5f;
        float x0f = floorf(gx), y0f = floorf(gy);
        float fx = gx - x0f, fy = gy - y0f;
        int x0 = (int)x0f, y0 = (int)y0f;
        float w = aw[p];
        corner(vb, x0,     y0,     m * 32, (1.f - fx) * (1.f - fy) * w, acc);
        corner(vb, x0 + 1, y0,     m * 32, fx * (1.f - fy) * w, acc);
        corner(vb, x0,     y0 + 1, m * 32, (1.f - fx) * fy * w, acc);
        corner(vb, x0 + 1, y0 + 1, m * 32, fx * fy * w, acc);
    }
    // S[b][ch*256 + m*32 + gh][gl]  (fp16)
    __half* S = g_S + (size_t)b * NG * 256 + (size_t)(m * 32 + gh) * 256 + gl;
#pragma unroll
    for (int ch = 0; ch < 32; ch++) S[(size_t)ch * 65536] = __float2half(acc[ch]);
}

extern "C" void kernel_launch(void* const* d_in, const int* in_sizes, int n_in,
                              void* d_out, int out_size) {
    const float* query  = (const float*)d_in[0];
    const float* value  = (const float*)d_in[1];
    const float* refp   = (const float*)d_in[2];
    const float* trajp  = (const float*)d_in[3];
    const float* in_w   = (const float*)d_in[4];
    const float* in_b   = (const float*)d_in[5];
    const float* mha_w  = (const float*)d_in[6];
    const float* mha_b  = (const float*)d_in[7];
    const float* ln_g   = (const float*)d_in[8];
    const float* ln_b   = (const float*)d_in[9];
    const float* traj_w = (const float*)d_in[10];
    const float* traj_b = (const float*)d_in[11];
    const float* offs_w = (const float*)d_in[12];
    const float* offs_b = (const float*)d_in[13];
    const float* attw_w = (const float*)d_in[14];
    const float* attw_b = (const float*)d_in[15];
    const float* out_w  = (const float*)d_in[16];
    const float* out_b  = (const float*)d_in[17];
    float* out = (float*)d_out;

    float *p_ctx, *p_oa, *p_wc, *p_bc;
    __half* p_S;
    cudaGetSymbolAddress((void**)&p_S,   g_S);
    cudaGetSymbolAddress((void**)&p_ctx, g_ctx);
    cudaGetSymbolAddress((void**)&p_oa,  g_oa);
    cudaGetSymbolAddress((void**)&p_wc,  g_wc);
    cudaGetSymbolAddress((void**)&p_bc,  g_bc);

    // (0) weight concat + rank-3 precomputes
    k_prep<<<97, 256>>>(offs_w, offs_b, attw_w, attw_b);
    k_precomp<<<1, 256>>>(in_w, in_b, traj_w, traj_b);
    k_precomp2<<<33, 256>>>(in_w, in_b, mha_w, mha_b);
    // (1) thin coef GEMM: coef[g,16] = query @ A^T + Ab
    k_coef<<<512, 128>>>(query);
    // (2) rank-3 attention -> g_R
    k_attn3<<<1024, 256>>>(trajp);
    // (3) fused mha-out(K=16) + residual + LN -> g_ctx
    k_ctxln<<<4096, 256>>>(query, ln_g, ln_b);
    // (4) offs + attw fused GEMM (scalar fp32), N=96
    gemm_bias<<<dim3(2, 256), 256>>>(p_ctx, p_wc, p_bc, p_oa, 96);
    // (5) value transpose to fp16 (B,H,W,C)
    k_transpose<<<dim3(32, 128, 4), dim3(32, 8)>>>(value);
    // (6) deformable sampling (fp16 scrambled S)
    k_sample<<<2048, 128>>>(refp);
    // (7) final projection via fp16 HMMA
    gemm_hmma<<<dim3(4, 256), 256>>>(p_S, out_w, out_b, out);
}

// round 12
// speedup vs baseline: 2.9271x; 1.0184x over previous
#include <cuda_runtime.h>
#include <cuda_fp16.h>
#include <math.h>
#include <stdint.h>

#define Bsz 4
#define NG  8192
#define Cdim 256
#define Hh  128
#define Ww  128
#define NT  512
#define EPSLN 1e-5f
#define ATTN_SCALE 0.17677669529663687f

__device__ __half g_S  [(size_t)Bsz*NG*Cdim];     // sampled S (fp16, 1x path)
__device__ float  g_ctx[Bsz*NG*Cdim];             // fused ctx+LN output
__device__ __half g_vt [(size_t)Bsz*Hh*Ww*Cdim];  // value transposed (B,H,W,C), fp16
__device__ float  g_oa [Bsz*NG*96];
__device__ float  g_wc [96*Cdim];
__device__ float  g_bc [96];
// rank-3 attention precomputes (gamma dropped: cancels in softmax ratio)
__device__ float  g_kv6[6*256];                   // Kx Ky K1 Vx Vy V1
__device__ float  g_A  [16*256];                  // coef weights (e = m*2+{x,y})
__device__ float  g_Ab [16];
__device__ float  g_Mw [16*256];                  // ctx->mha weights (e = m*2+{x,y})
__device__ float  g_Mc [256];                     // const vector (V1 path + mha_b)
__device__ float  g_coef[(size_t)Bsz*NG*16];
__device__ float  g_R  [(size_t)Bsz*NG*16];

// ---- weight concat (offs|attw) ----
__global__ __launch_bounds__(256) void k_prep(const float* __restrict__ ow,
                                              const float* __restrict__ ob,
                                              const float* __restrict__ aw,
                                              const float* __restrict__ ab) {
    int i = blockIdx.x * 256 + threadIdx.x;
    if (i < 64 * 256)                 g_wc[i] = ow[i];
    else if (i < 96 * 256)            g_wc[i] = aw[i - 64 * 256];
    else if (i < 96 * 256 + 64)       g_bc[i - 96 * 256] = ob[i - 96 * 256];
    else if (i < 96 * 256 + 96)       g_bc[i - 96 * 256] = ab[i - 96 * 256 - 64];
}

// ---- rank-3 K/V basis: 6 blocks, one per output vector ----
__global__ __launch_bounds__(256) void k_precomp(const float* __restrict__ in_w,
                                                 const float* __restrict__ in_b,
                                                 const float* __restrict__ tw,
                                                 const float* __restrict__ tb) {
    __shared__ float stw[256];
    int bi = blockIdx.x;            // 0..5 : Kx Ky K1 Vx Vy V1
    int c = threadIdx.x;
    int comp = bi % 3;
    int wrow = (bi < 3) ? (256 + c) : (512 + c);
    stw[c] = (comp == 0) ? tw[c * 2] : (comp == 1) ? tw[c * 2 + 1] : tb[c];
    __syncthreads();
    const float4* wp = (const float4*)(in_w + (size_t)wrow * 256);
    float acc = 0.f;
#pragma unroll 8
    for (int j = 0; j < 64; j++) {
        float4 v = wp[j];
        acc = fmaf(v.x, stw[j * 4],     acc);
        acc = fmaf(v.y, stw[j * 4 + 1], acc);
        acc = fmaf(v.z, stw[j * 4 + 2], acc);
        acc = fmaf(v.w, stw[j * 4 + 3], acc);
    }
    if (bi == 2) acc += in_b[256 + c];
    if (bi == 5) acc += in_b[512 + c];
    g_kv6[bi * 256 + c] = acc;
}

// ---- fold q-proj into coef weights A (x,y only), mha-out into Mw/Mc ----
__global__ __launch_bounds__(256) void k_precomp2(const float* __restrict__ in_w,
                                                  const float* __restrict__ in_b,
                                                  const float* __restrict__ mw,
                                                  const float* __restrict__ mb) {
    int bi = blockIdx.x, t = threadIdx.x;
    if (bi < 16) {                       // A[e][j] = sum_c wq[m*32+c][j] * KC[comp][m*32+c]
        int m = bi >> 1, comp = bi & 1;
        const float* KC = g_kv6 + comp * 256 + m * 32;
        float a = 0.f;
#pragma unroll 8
        for (int c = 0; c < 32; c++)
            a = fmaf(in_w[(size_t)(m * 32 + c) * 256 + t], KC[c], a);
        g_A[bi * 256 + t] = a * ATTN_SCALE;
        if (t < 32) {
            float v = in_b[m * 32 + t] * KC[t];
#pragma unroll
            for (int o = 16; o; o >>= 1) v += __shfl_xor_sync(0xffffffffu, v, o);
            if (t == 0) g_Ab[bi] = v * ATTN_SCALE;
        }
    } else if (bi < 32) {                // Mw[e2][o] = sum_c mha_w[o][m*32+c] * VC[comp][..]
        int e2 = bi - 16, m = e2 >> 1, comp = e2 & 1;
        const float* VC = g_kv6 + (3 + comp) * 256 + m * 32;
        const float* mwr = mw + (size_t)t * 256 + m * 32;
        float a = 0.f;
#pragma unroll 8
        for (int c = 0; c < 32; c++) a = fmaf(mwr[c], VC[c], a);
        g_Mw[e2 * 256 + t] = a;
    } else {                             // Mc[o] = sum_c mha_w[o][c]*V1[c] + mha_b[o]
        const float* V1 = g_kv6 + 5 * 256;
        const float* mwr = mw + (size_t)t * 256;
        float a = mb[t];
        for (int c = 0; c < 256; c++) a = fmaf(mwr[c], V1[c], a);
        g_Mc[t] = a;
    }
}

// ---- thin coef GEMM v2: 256 thr, 4 thr/row, register-batched loads ----
__global__ __launch_bounds__(256) void k_coef(const float* __restrict__ q) {
    __shared__ float sA[256][17];   // sA[k][e]
    __shared__ float sAb[16];
    int tid = threadIdx.x;
    for (int i = tid; i < 4096; i += 256) sA[i & 255][i >> 8] = g_A[i];
    if (tid < 16) sAb[tid] = g_Ab[tid];
    __syncthreads();

    int row = blockIdx.x * 64 + (tid >> 2);
    int qt = tid & 3;               // quarter of K: [qt*64, qt*64+64)
    const float4* qp = (const float4*)(q + (size_t)row * 256 + qt * 64);
    float acc[16];
#pragma unroll
    for (int e = 0; e < 16; e++) acc[e] = 0.f;

#pragma unroll
    for (int half = 0; half < 2; half++) {
        float4 v[8];
#pragma unroll
        for (int i = 0; i < 8; i++) v[i] = qp[half * 8 + i];
#pragma unroll
        for (int i = 0; i < 8; i++) {
            int k = qt * 64 + half * 32 + i * 4;
#pragma unroll
            for (int e = 0; e < 16; e++) {
                acc[e] = fmaf(v[i].x, sA[k][e],     acc[e]);
                acc[e] = fmaf(v[i].y, sA[k + 1][e], acc[e]);
                acc[e] = fmaf(v[i].z, sA[k + 2][e], acc[e]);
                acc[e] = fmaf(v[i].w, sA[k + 3][e], acc[e]);
            }
        }
    }
#pragma unroll
    for (int e = 0; e < 16; e++) {
        acc[e] += __shfl_xor_sync(0xffffffffu, acc[e], 1);
        acc[e] += __shfl_xor_sync(0xffffffffu, acc[e], 2);
    }
    int e0 = qt * 4;
    float4 o;
    o.x = acc[e0]     + sAb[e0];
    o.y = acc[e0 + 1] + sAb[e0 + 1];
    o.z = acc[e0 + 2] + sAb[e0 + 2];
    o.w = acc[e0 + 3] + sAb[e0 + 3];
    *(float4*)(g_coef + (size_t)row * 16 + e0) = o;
}

// ---- rank-3 attention: thread = (query, head); gamma-free scores ----
__global__ __launch_bounds__(256) void k_attn3(const float* __restrict__ tp) {
    __shared__ float sxy[NT * 2];
    int bi = blockIdx.x;                  // 1024 = B * 256
    int b = bi >> 8, qt = bi & 255;
    int tid = threadIdx.x;
    for (int t = tid; t < NT; t += 256) {
        float2 v = ((const float2*)tp)[b * NT + t];
        sxy[t * 2] = v.x; sxy[t * 2 + 1] = v.y;
    }
    __syncthreads();

    int m = tid & 7;
    int g = qt * 32 + (tid >> 3);
    size_t gi = (size_t)b * NG + g;
    const float* cf = g_coef + gi * 16 + m * 2;
    float al = cf[0], be = cf[1];
    float Sp = 0.f, Sx = 0.f, Sy = 0.f;
#pragma unroll 4
    for (int t = 0; t < NT; t++) {
        float2 xy = ((const float2*)sxy)[t];
        float s = fmaf(al, xy.x, be * xy.y);
        float p = __expf(s);
        Sp += p;
        Sx = fmaf(p, xy.x, Sx);
        Sy = fmaf(p, xy.y, Sy);
    }
    float inv = 1.f / Sp;
    float2 r = {Sx * inv, Sy * inv};
    ((float2*)(g_R + gi * 16))[m] = r;
}

// ---- fused mha-out (K=16) + residual + LayerNorm -> g_ctx ----
__global__ __launch_bounds__(256) void k_ctxln(const float* __restrict__ q_in,
                                               const float* __restrict__ lng,
                                               const float* __restrict__ lnb) {
    __shared__ float sMw[16][256];
    __shared__ float sR[8][16];
    __shared__ float sMc[256];
    __shared__ float red[8][8];
    int tid = threadIdx.x;
    int r0 = blockIdx.x * 8;
#pragma unroll
    for (int k = 0; k < 16; k++) sMw[k][tid] = g_Mw[k * 256 + tid];
    sMc[tid] = g_Mc[tid];
    if (tid < 128) {
        int r = tid >> 4, k = tid & 15;
        sR[r][k] = g_R[(size_t)(r0 + r) * 16 + k];
    }
    __syncthreads();

    float xv[8];
#pragma unroll
    for (int r = 0; r < 8; r++) {
        float acc = sMc[tid];
#pragma unroll
        for (int k = 0; k < 16; k++) acc = fmaf(sR[r][k], sMw[k][tid], acc);
        xv[r] = acc + q_in[(size_t)(r0 + r) * 256 + tid];
    }
    int lane = tid & 31, w = tid >> 5;
#pragma unroll
    for (int r = 0; r < 8; r++) {
        float s = xv[r];
#pragma unroll
        for (int o = 16; o; o >>= 1) s += __shfl_xor_sync(0xffffffffu, s, o);
        if (!lane) red[w][r] = s;
    }
    __syncthreads();
    float mu[8];
#pragma unroll
    for (int r = 0; r < 8; r++) {
        float tot = 0.f;
#pragma unroll
        for (int i = 0; i < 8; i++) tot += red[i][r];
        mu[r] = tot * (1.f / 256.f);
    }
    __syncthreads();
#pragma unroll
    for (int r = 0; r < 8; r++) {
        float d = xv[r] - mu[r];
        float s = d * d;
#pragma unroll
        for (int o = 16; o; o >>= 1) s += __shfl_xor_sync(0xffffffffu, s, o);
        if (!lane) red[w][r] = s;
    }
    __syncthreads();
    float gg = lng[tid], bb = lnb[tid];
#pragma unroll
    for (int r = 0; r < 8; r++) {
        float tot = 0.f;
#pragma unroll
        for (int i = 0; i < 8; i++) tot += red[i][r];
        float inv = rsqrtf(tot * (1.f / 256.f) + EPSLN);
        g_ctx[(size_t)(r0 + r) * 256 + tid] = (xv[r] - mu[r]) * inv * gg + bb;
    }
}

// ---- scalar fp32 GEMM (offs/attw: fp32-precision path) ----
__global__ __launch_bounds__(256) void gemm_bias(const float* __restrict__ X,
                                                 const float* __restrict__ W,
                                                 const float* __restrict__ bias,
                                                 float* __restrict__ Y, int N) {
    __shared__ __align__(16) float As[16][132];
    __shared__ __align__(16) float Bs[16][68];
    int tid = threadIdx.x;
    int row0 = blockIdx.y * 128, n0 = blockIdx.x * 64;
    int rg = tid >> 4, cg = tid & 15;
    float acc[8][4];
#pragma unroll
    for (int i = 0; i < 8; i++)
#pragma unroll
        for (int j = 0; j < 4; j++) acc[i][j] = 0.f;

    int ar = tid >> 1, akq = (tid & 1) * 8;
    int bn = tid >> 2, bkq = (tid & 3) * 4;
    bool bvalid = (n0 + bn) < N;
    const float* Xp = X + (size_t)(row0 + ar) * 256 + akq;
    const float* Wp = W + (size_t)(bvalid ? (n0 + bn) : 0) * 256 + bkq;

    for (int kt = 0; kt < 16; kt++) {
        int k0 = kt * 16;
        float4 a0 = *(const float4*)(Xp + k0);
        float4 a1 = *(const float4*)(Xp + k0 + 4);
        float4 b0 = bvalid ? *(const float4*)(Wp + k0) : make_float4(0.f, 0.f, 0.f, 0.f);
        As[akq + 0][ar] = a0.x; As[akq + 1][ar] = a0.y;
        As[akq + 2][ar] = a0.z; As[akq + 3][ar] = a0.w;
        As[akq + 4][ar] = a1.x; As[akq + 5][ar] = a1.y;
        As[akq + 6][ar] = a1.z; As[akq + 7][ar] = a1.w;
        Bs[bkq + 0][bn] = b0.x; Bs[bkq + 1][bn] = b0.y;
        Bs[bkq + 2][bn] = b0.z; Bs[bkq + 3][bn] = b0.w;
        __syncthreads();
#pragma unroll
        for (int kk = 0; kk < 16; kk++) {
            float4 av0 = *(const float4*)&As[kk][rg * 8];
            float4 av1 = *(const float4*)&As[kk][rg * 8 + 4];
            float4 bv  = *(const float4*)&Bs[kk][cg * 4];
            float a[8] = {av0.x, av0.y, av0.z, av0.w, av1.x, av1.y, av1.z, av1.w};
            float bb[4] = {bv.x, bv.y, bv.z, bv.w};
#pragma unroll
            for (int i = 0; i < 8; i++)
#pragma unroll
                for (int j = 0; j < 4; j++) acc[i][j] = fmaf(a[i], bb[j], acc[i][j]);
        }
        __syncthreads();
    }
    int nc = n0 + cg * 4;
    if (nc < N) {
        float4 bb = *(const float4*)(bias + nc);
#pragma unroll
        for (int i = 0; i < 8; i++) {
            float4 o;
            o.x = acc[i][0] + bb.x; o.y = acc[i][1] + bb.y;
            o.z = acc[i][2] + bb.z; o.w = acc[i][3] + bb.w;
            *(float4*)(Y + (size_t)(row0 + rg * 8 + i) * N + nc) = o;
        }
    }
}

// ---- fp16 HMMA final projection: Y[32768x256] = S(half) @ W^T + bias ----
__global__ __launch_bounds__(256) void gemm_hmma(const __half* __restrict__ X,
                                                 const float* __restrict__ W,
                                                 const float* __restrict__ bias,
                                                 float* __restrict__ Y) {
    __shared__ __half Ah[128][40];
    __shared__ __half Bh[64][40];
    int tid = threadIdx.x;
    int row0 = blockIdx.y * 128, n0b = blockIdx.x * 64;
    int w = tid >> 5, lane = tid & 31, grp = lane >> 2, qid = lane & 3;
    float acc[8][4];
#pragma unroll
    for (int j = 0; j < 8; j++)
#pragma unroll
        for (int i = 0; i < 4; i++) acc[j][i] = 0.f;

    int ar = tid >> 1, aseg = (tid & 1) * 16;
    int br = tid >> 2, bq = (tid & 3) * 8;
    const __half* Xp = X + (size_t)(row0 + ar) * 256 + aseg;
    const float* Wp = W + (size_t)(n0b + br) * 256 + bq;

    for (int kt = 0; kt < 8; kt++) {
        int k0t = kt * 32;
        {
            uint4 v0 = *(const uint4*)(Xp + k0t);
            uint4 v1 = *(const uint4*)(Xp + k0t + 8);
            *(uint4*)&Ah[ar][aseg] = v0;
            *(uint4*)&Ah[ar][aseg + 8] = v1;
        }
        {
            float4 v0 = *(const float4*)(Wp + k0t);
            float4 v1 = *(const float4*)(Wp + k0t + 4);
            __half2 h[4];
            h[0] = __floats2half2_rn(v0.x, v0.y); h[1] = __floats2half2_rn(v0.z, v0.w);
            h[2] = __floats2half2_rn(v1.x, v1.y); h[3] = __floats2half2_rn(v1.z, v1.w);
            *(uint4*)&Bh[br][bq] = *(uint4*)h;
        }
        __syncthreads();
#pragma unroll
        for (int ks = 0; ks < 2; ks++) {
            int k0 = ks * 16;
            uint32_t a0 = *(const uint32_t*)&Ah[w * 16 + grp][k0 + qid * 2];
            uint32_t a1 = *(const uint32_t*)&Ah[w * 16 + grp + 8][k0 + qid * 2];
            uint32_t a2 = *(const uint32_t*)&Ah[w * 16 + grp][k0 + qid * 2 + 8];
            uint32_t a3 = *(const uint32_t*)&Ah[w * 16 + grp + 8][k0 + qid * 2 + 8];
#pragma unroll
            for (int j = 0; j < 8; j++) {
                uint32_t b0 = *(const uint32_t*)&Bh[j * 8 + grp][k0 + qid * 2];
                uint32_t b1 = *(const uint32_t*)&Bh[j * 8 + grp][k0 + qid * 2 + 8];
                asm volatile(
                    "mma.sync.aligned.m16n8k16.row.col.f32.f16.f16.f32 "
                    "{%0,%1,%2,%3}, {%4,%5,%6,%7}, {%8,%9}, {%0,%1,%2,%3};"
                    : "+f"(acc[j][0]), "+f"(acc[j][1]), "+f"(acc[j][2]), "+f"(acc[j][3])
                    : "r"(a0), "r"(a1), "r"(a2), "r"(a3), "r"(b0), "r"(b1));
            }
        }
        __syncthreads();
    }
    int r = row0 + w * 16 + grp;
#pragma unroll
    for (int j = 0; j < 8; j++) {
        int c = n0b + j * 8 + qid * 2;
        float2 bb = *(const float2*)(bias + c);
        float2 o0 = {acc[j][0] + bb.x, acc[j][1] + bb.y};
        float2 o1 = {acc[j][2] + bb.x, acc[j][3] + bb.y};
        *(float2*)(Y + (size_t)r * 256 + c) = o0;
        *(float2*)(Y + (size_t)(r + 8) * 256 + c) = o1;
    }
}

// ---- value (B,C,H,W) fp32 -> (B,H,W,C) fp16 ----
__global__ __launch_bounds__(256) void k_transpose(const float* __restrict__ val) {
    __shared__ float tile[32][33];
    int tx = threadIdx.x, ty = threadIdx.y;
    int b = blockIdx.z, y = blockIdx.y;
    int c0 = (blockIdx.x >> 2) * 32, x0 = (blockIdx.x & 3) * 32;
#pragma unroll
    for (int i = 0; i < 4; i++)
        tile[ty + i * 8][tx] = val[(((size_t)(b * Cdim + c0 + ty + i * 8) * Hh + y) * Ww) + x0 + tx];
    __syncthreads();
#pragma unroll
    for (int i = 0; i < 4; i++)
        g_vt[(((size_t)(b * Hh + y) * Ww + x0 + ty + i * 8) * Cdim) + c0 + tx] =
            __float2half(tile[tx][ty + i * 8]);
}

// ---- bilinear corner accumulate (fp16 values, fp32 math) ----
__device__ __forceinline__ void corner(const __half* __restrict__ vb, int x, int y,
                                       int moff, float w, float* acc) {
    if (x < 0 || x >= Ww || y < 0 || y >= Hh) return;
    const uint4* p = (const uint4*)(vb + ((size_t)(y * Ww + x)) * Cdim + moff);
#pragma unroll
    for (int i = 0; i < 4; i++) {
        uint4 u = p[i];
        const __half2* h = (const __half2*)&u;
#pragma unroll
        for (int j = 0; j < 4; j++) {
            float2 f = __half22float2(h[j]);
            acc[i * 8 + j * 2]     = fmaf(w, f.x, acc[i * 8 + j * 2]);
            acc[i * 8 + j * 2 + 1] = fmaf(w, f.y, acc[i * 8 + j * 2 + 1]);
        }
    }
}

// ---- deformable sampling: thread = (query, m); scrambled fp16 store into g_S ----
__global__ __launch_bounds__(128) void k_sample(const float* __restrict__ refp) {
    int bi = blockIdx.x;            // 2048 = B * 8 * 64
    int tid = threadIdx.x;
    int b = bi >> 9;
    int m = (bi >> 6) & 7;
    int gg = (bi & 63) * 128 + tid;
    int gh = gg >> 8, gl = gg & 255;
    size_t qidx = (size_t)b * NG + gg;
    float rx = refp[qidx * 2], ry = refp[qidx * 2 + 1];
    const float* oar = g_oa + qidx * 96;

    float a0 = oar[64 + m * 4], a1 = oar[64 + m * 4 + 1];
    float a2 = oar[64 + m * 4 + 2], a3 = oar[64 + m * 4 + 3];
    float amx = fmaxf(fmaxf(a0, a1), fmaxf(a2, a3));
    float e0 = __expf(a0 - amx), e1 = __expf(a1 - amx);
    float e2 = __expf(a2 - amx), e3 = __expf(a3 - amx);
    float inv = 1.f / (e0 + e1 + e2 + e3);
    float aw[4] = {e0 * inv, e1 * inv, e2 * inv, e3 * inv};

    const __half* vb = g_vt + (size_t)b * Hh * Ww * Cdim;
    float acc[32];
#pragma unroll
    for (int i = 0; i < 32; i++) acc[i] = 0.f;

#pragma unroll
    for (int p = 0; p < 4; p++) {
        float gx = (rx + oar[m * 8 + p * 2]) * (float)Ww - 0.5f;
        float gy = (ry + oar[m * 8 + p * 2 + 1]) * (float)Hh - 0.5f;
        float x0f = floorf(gx), y0f = floorf(gy);
        float fx = gx - x0f, fy = gy - y0f;
        int x0 = (int)x0f, y0 = (int)y0f;
        float w = aw[p];
        corner(vb, x0,     y0,     m * 32, (1.f - fx) * (1.f - fy) * w, acc);
        corner(vb, x0 + 1, y0,     m * 32, fx * (1.f - fy) * w, acc);
        corner(vb, x0,     y0 + 1, m * 32, (1.f - fx) * fy * w, acc);
        corner(vb, x0 + 1, y0 + 1, m * 32, fx * fy * w, acc);
    }
    // S[b][ch*256 + m*32 + gh][gl]  (fp16)
    __half* S = g_S + (size_t)b * NG * 256 + (size_t)(m * 32 + gh) * 256 + gl;
#pragma unroll
    for (int ch = 0; ch < 32; ch++) S[(size_t)ch * 65536] = __float2half(acc[ch]);
}

extern "C" void kernel_launch(void* const* d_in, const int* in_sizes, int n_in,
                              void* d_out, int out_size) {
    const float* query  = (const float*)d_in[0];
    const float* value  = (const float*)d_in[1];
    const float* refp   = (const float*)d_in[2];
    const float* trajp  = (const float*)d_in[3];
    const float* in_w   = (const float*)d_in[4];
    const float* in_b   = (const float*)d_in[5];
    const float* mha_w  = (const float*)d_in[6];
    const float* mha_b  = (const float*)d_in[7];
    const float* ln_g   = (const float*)d_in[8];
    const float* ln_b   = (const float*)d_in[9];
    const float* traj_w = (const float*)d_in[10];
    const float* traj_b = (const float*)d_in[11];
    const float* offs_w = (const float*)d_in[12];
    const float* offs_b = (const float*)d_in[13];
    const float* attw_w = (const float*)d_in[14];
    const float* attw_b = (const float*)d_in[15];
    const float* out_w  = (const float*)d_in[16];
    const float* out_b  = (const float*)d_in[17];
    float* out = (float*)d_out;

    float *p_ctx, *p_oa, *p_wc, *p_bc;
    __half* p_S;
    cudaGetSymbolAddress((void**)&p_S,   g_S);
    cudaGetSymbolAddress((void**)&p_ctx, g_ctx);
    cudaGetSymbolAddress((void**)&p_oa,  g_oa);
    cudaGetSymbolAddress((void**)&p_wc,  g_wc);
    cudaGetSymbolAddress((void**)&p_bc,  g_bc);

    // (0) weight concat + rank-3 precomputes
    k_prep<<<97, 256>>>(offs_w, offs_b, attw_w, attw_b);
    k_precomp<<<6, 256>>>(in_w, in_b, traj_w, traj_b);
    k_precomp2<<<33, 256>>>(in_w, in_b, mha_w, mha_b);
    // (1) thin coef GEMM: coef[g,16] = query @ A^T + Ab
    k_coef<<<512, 256>>>(query);
    // (2) rank-3 attention -> g_R
    k_attn3<<<1024, 256>>>(trajp);
    // (3) fused mha-out(K=16) + residual + LN -> g_ctx
    k_ctxln<<<4096, 256>>>(query, ln_g, ln_b);
    // (4) offs + attw fused GEMM (scalar fp32), N=96
    gemm_bias<<<dim3(2, 256), 256>>>(p_ctx, p_wc, p_bc, p_oa, 96);
    // (5) value transpose to fp16 (B,H,W,C)
    k_transpose<<<dim3(32, 128, 4), dim3(32, 8)>>>(value);
    // (6) deformable sampling (fp16 scrambled S)
    k_sample<<<2048, 128>>>(refp);
    // (7) final projection via fp16 HMMA
    gemm_hmma<<<dim3(4, 256), 256>>>(p_S, out_w, out_b, out);
}

// round 13
// speedup vs baseline: 3.3520x; 1.1452x over previous
#include <cuda_runtime.h>
#include <cuda_fp16.h>
#include <math.h>
#include <stdint.h>

#define Bsz 4
#define NG  8192
#define Cdim 256
#define Hh  128
#define Ww  128
#define NT  512
#define EPSLN 1e-5f
#define ATTN_SCALE 0.17677669529663687f

__device__ __half g_S  [(size_t)Bsz*NG*Cdim];     // sampled S (fp16, 1x path)
__device__ float  g_ctx[Bsz*NG*Cdim];             // fused ctx+LN output
__device__ __half g_vt [(size_t)Bsz*Hh*Ww*Cdim];  // value transposed (B,H,W,C), fp16
__device__ float  g_oa [Bsz*NG*96];
__device__ float  g_wc [96*Cdim];
__device__ float  g_bc [96];
// rank-3 attention precomputes (gamma dropped: cancels in softmax ratio)
__device__ float  g_kv6[6*256];                   // Kx Ky K1 Vx Vy V1
__device__ float  g_A  [16*256];                  // coef weights (e = m*2+{x,y})
__device__ float  g_Ab [16];
__device__ float  g_Mw [16*256];                  // ctx->mha weights (e = m*2+{x,y})
__device__ float  g_Mc [256];                     // const vector (V1 path + mha_b)
__device__ float  g_coef[(size_t)Bsz*NG*16];
__device__ float  g_R  [(size_t)Bsz*NG*16];

// ---- weight concat (offs|attw) ----
__global__ __launch_bounds__(256) void k_prep(const float* __restrict__ ow,
                                              const float* __restrict__ ob,
                                              const float* __restrict__ aw,
                                              const float* __restrict__ ab) {
    int i = blockIdx.x * 256 + threadIdx.x;
    if (i < 64 * 256)                 g_wc[i] = ow[i];
    else if (i < 96 * 256)            g_wc[i] = aw[i - 64 * 256];
    else if (i < 96 * 256 + 64)       g_bc[i - 96 * 256] = ob[i - 96 * 256];
    else if (i < 96 * 256 + 96)       g_bc[i - 96 * 256] = ab[i - 96 * 256 - 64];
}

// ---- rank-3 K/V basis: 6 blocks, one per output vector ----
__global__ __launch_bounds__(256) void k_precomp(const float* __restrict__ in_w,
                                                 const float* __restrict__ in_b,
                                                 const float* __restrict__ tw,
                                                 const float* __restrict__ tb) {
    __shared__ float stw[256];
    int bi = blockIdx.x;            // 0..5 : Kx Ky K1 Vx Vy V1
    int c = threadIdx.x;
    int comp = bi % 3;
    int wrow = (bi < 3) ? (256 + c) : (512 + c);
    stw[c] = (comp == 0) ? tw[c * 2] : (comp == 1) ? tw[c * 2 + 1] : tb[c];
    __syncthreads();
    const float4* wp = (const float4*)(in_w + (size_t)wrow * 256);
    float acc = 0.f;
#pragma unroll 8
    for (int j = 0; j < 64; j++) {
        float4 v = wp[j];
        acc = fmaf(v.x, stw[j * 4],     acc);
        acc = fmaf(v.y, stw[j * 4 + 1], acc);
        acc = fmaf(v.z, stw[j * 4 + 2], acc);
        acc = fmaf(v.w, stw[j * 4 + 3], acc);
    }
    if (bi == 2) acc += in_b[256 + c];
    if (bi == 5) acc += in_b[512 + c];
    g_kv6[bi * 256 + c] = acc;
}

// ---- fold q-proj into coef weights A (x,y only), mha-out into Mw/Mc ----
__global__ __launch_bounds__(256) void k_precomp2(const float* __restrict__ in_w,
                                                  const float* __restrict__ in_b,
                                                  const float* __restrict__ mw,
                                                  const float* __restrict__ mb) {
    int bi = blockIdx.x, t = threadIdx.x;
    if (bi < 16) {                       // A[e][j] = sum_c wq[m*32+c][j] * KC[comp][m*32+c]
        int m = bi >> 1, comp = bi & 1;
        const float* KC = g_kv6 + comp * 256 + m * 32;
        float a = 0.f;
#pragma unroll 8
        for (int c = 0; c < 32; c++)
            a = fmaf(in_w[(size_t)(m * 32 + c) * 256 + t], KC[c], a);
        g_A[bi * 256 + t] = a * ATTN_SCALE;
        if (t < 32) {
            float v = in_b[m * 32 + t] * KC[t];
#pragma unroll
            for (int o = 16; o; o >>= 1) v += __shfl_xor_sync(0xffffffffu, v, o);
            if (t == 0) g_Ab[bi] = v * ATTN_SCALE;
        }
    } else if (bi < 32) {                // Mw[e2][o] = sum_c mha_w[o][m*32+c] * VC[comp][..]
        int e2 = bi - 16, m = e2 >> 1, comp = e2 & 1;
        const float* VC = g_kv6 + (3 + comp) * 256 + m * 32;
        const float* mwr = mw + (size_t)t * 256 + m * 32;
        float a = 0.f;
#pragma unroll 8
        for (int c = 0; c < 32; c++) a = fmaf(mwr[c], VC[c], a);
        g_Mw[e2 * 256 + t] = a;
    } else {                             // Mc[o] = sum_c mha_w[o][c]*V1[c] + mha_b[o]
        const float* V1 = g_kv6 + 5 * 256;
        const float* mwr = mw + (size_t)t * 256;
        float a = mb[t];
        for (int c = 0; c < 256; c++) a = fmaf(mwr[c], V1[c], a);
        g_Mc[t] = a;
    }
}

// ---- thin coef GEMM v3: k-outer, vectorized-broadcast A, 2 thr/row ----
__global__ __launch_bounds__(256) void k_coef(const float* __restrict__ q) {
    __shared__ float sA[256][16];   // sA[k][e], e contiguous -> LDS.128 broadcast
    __shared__ float sAb[16];
    int tid = threadIdx.x;
    for (int i = tid; i < 4096; i += 256) sA[i & 255][i >> 8] = g_A[i];
    if (tid < 16) sAb[tid] = g_Ab[tid];
    __syncthreads();

    int row = blockIdx.x * 128 + (tid >> 1);
    int h = tid & 1;                // k-half: [h*128, h*128+128)
    const float4* qp = (const float4*)(q + (size_t)row * 256 + h * 128);
    float acc[16];
#pragma unroll
    for (int e = 0; e < 16; e++) acc[e] = 0.f;

#pragma unroll 2
    for (int i = 0; i < 32; i += 4) {
        float4 v[4];
#pragma unroll
        for (int j = 0; j < 4; j++) v[j] = qp[i + j];
#pragma unroll
        for (int j = 0; j < 4; j++) {
            int kb = h * 128 + (i + j) * 4;
            const float* vv = (const float*)&v[j];
#pragma unroll
            for (int s = 0; s < 4; s++) {
                float val = vv[s];
                const float4* ap = (const float4*)sA[kb + s];
                float4 a0 = ap[0], a1 = ap[1], a2 = ap[2], a3 = ap[3];
                acc[0]  = fmaf(val, a0.x, acc[0]);  acc[1]  = fmaf(val, a0.y, acc[1]);
                acc[2]  = fmaf(val, a0.z, acc[2]);  acc[3]  = fmaf(val, a0.w, acc[3]);
                acc[4]  = fmaf(val, a1.x, acc[4]);  acc[5]  = fmaf(val, a1.y, acc[5]);
                acc[6]  = fmaf(val, a1.z, acc[6]);  acc[7]  = fmaf(val, a1.w, acc[7]);
                acc[8]  = fmaf(val, a2.x, acc[8]);  acc[9]  = fmaf(val, a2.y, acc[9]);
                acc[10] = fmaf(val, a2.z, acc[10]); acc[11] = fmaf(val, a2.w, acc[11]);
                acc[12] = fmaf(val, a3.x, acc[12]); acc[13] = fmaf(val, a3.y, acc[13]);
                acc[14] = fmaf(val, a3.z, acc[14]); acc[15] = fmaf(val, a3.w, acc[15]);
            }
        }
    }
    // combine the two k-halves (lanes h=0/1 of each pair)
#pragma unroll
    for (int e = 0; e < 16; e++)
        acc[e] += __shfl_xor_sync(0xffffffffu, acc[e], 1);
    // lane h stores e in [h*8, h*8+8)
    int e0 = h * 8;
    float4 o0, o1;
    o0.x = acc[e0]     + sAb[e0];     o0.y = acc[e0 + 1] + sAb[e0 + 1];
    o0.z = acc[e0 + 2] + sAb[e0 + 2]; o0.w = acc[e0 + 3] + sAb[e0 + 3];
    o1.x = acc[e0 + 4] + sAb[e0 + 4]; o1.y = acc[e0 + 5] + sAb[e0 + 5];
    o1.z = acc[e0 + 6] + sAb[e0 + 6]; o1.w = acc[e0 + 7] + sAb[e0 + 7];
    *(float4*)(g_coef + (size_t)row * 16 + e0)     = o0;
    *(float4*)(g_coef + (size_t)row * 16 + e0 + 4) = o1;
}

// ---- rank-3 attention: thread = (query, head); gamma-free scores ----
__global__ __launch_bounds__(256) void k_attn3(const float* __restrict__ tp) {
    __shared__ float sxy[NT * 2];
    int bi = blockIdx.x;                  // 1024 = B * 256
    int b = bi >> 8, qt = bi & 255;
    int tid = threadIdx.x;
    for (int t = tid; t < NT; t += 256) {
        float2 v = ((const float2*)tp)[b * NT + t];
        sxy[t * 2] = v.x; sxy[t * 2 + 1] = v.y;
    }
    __syncthreads();

    int m = tid & 7;
    int g = qt * 32 + (tid >> 3);
    size_t gi = (size_t)b * NG + g;
    const float* cf = g_coef + gi * 16 + m * 2;
    float al = cf[0], be = cf[1];
    float Sp = 0.f, Sx = 0.f, Sy = 0.f;
#pragma unroll 4
    for (int t = 0; t < NT; t++) {
        float2 xy = ((const float2*)sxy)[t];
        float s = fmaf(al, xy.x, be * xy.y);
        float p = __expf(s);
        Sp += p;
        Sx = fmaf(p, xy.x, Sx);
        Sy = fmaf(p, xy.y, Sy);
    }
    float inv = 1.f / Sp;
    float2 r = {Sx * inv, Sy * inv};
    ((float2*)(g_R + gi * 16))[m] = r;
}

// ---- fused mha-out (K=16) + residual + LayerNorm -> g_ctx ----
__global__ __launch_bounds__(256) void k_ctxln(const float* __restrict__ q_in,
                                               const float* __restrict__ lng,
                                               const float* __restrict__ lnb) {
    __shared__ float sMw[16][256];
    __shared__ float sR[8][16];
    __shared__ float sMc[256];
    __shared__ float red[8][8];
    int tid = threadIdx.x;
    int r0 = blockIdx.x * 8;
#pragma unroll
    for (int k = 0; k < 16; k++) sMw[k][tid] = g_Mw[k * 256 + tid];
    sMc[tid] = g_Mc[tid];
    if (tid < 128) {
        int r = tid >> 4, k = tid & 15;
        sR[r][k] = g_R[(size_t)(r0 + r) * 16 + k];
    }
    __syncthreads();

    float xv[8];
#pragma unroll
    for (int r = 0; r < 8; r++) {
        float acc = sMc[tid];
#pragma unroll
        for (int k = 0; k < 16; k++) acc = fmaf(sR[r][k], sMw[k][tid], acc);
        xv[r] = acc + q_in[(size_t)(r0 + r) * 256 + tid];
    }
    int lane = tid & 31, w = tid >> 5;
#pragma unroll
    for (int r = 0; r < 8; r++) {
        float s = xv[r];
#pragma unroll
        for (int o = 16; o; o >>= 1) s += __shfl_xor_sync(0xffffffffu, s, o);
        if (!lane) red[w][r] = s;
    }
    __syncthreads();
    float mu[8];
#pragma unroll
    for (int r = 0; r < 8; r++) {
        float tot = 0.f;
#pragma unroll
        for (int i = 0; i < 8; i++) tot += red[i][r];
        mu[r] = tot * (1.f / 256.f);
    }
    __syncthreads();
#pragma unroll
    for (int r = 0; r < 8; r++) {
        float d = xv[r] - mu[r];
        float s = d * d;
#pragma unroll
        for (int o = 16; o; o >>= 1) s += __shfl_xor_sync(0xffffffffu, s, o);
        if (!lane) red[w][r] = s;
    }
    __syncthreads();
    float gg = lng[tid], bb = lnb[tid];
#pragma unroll
    for (int r = 0; r < 8; r++) {
        float tot = 0.f;
#pragma unroll
        for (int i = 0; i < 8; i++) tot += red[i][r];
        float inv = rsqrtf(tot * (1.f / 256.f) + EPSLN);
        g_ctx[(size_t)(r0 + r) * 256 + tid] = (xv[r] - mu[r]) * inv * gg + bb;
    }
}

// ---- scalar fp32 GEMM (offs/attw: fp32-precision path) ----
__global__ __launch_bounds__(256) void gemm_bias(const float* __restrict__ X,
                                                 const float* __restrict__ W,
                                                 const float* __restrict__ bias,
                                                 float* __restrict__ Y, int N) {
    __shared__ __align__(16) float As[16][132];
    __shared__ __align__(16) float Bs[16][68];
    int tid = threadIdx.x;
    int row0 = blockIdx.y * 128, n0 = blockIdx.x * 64;
    int rg = tid >> 4, cg = tid & 15;
    float acc[8][4];
#pragma unroll
    for (int i = 0; i < 8; i++)
#pragma unroll
        for (int j = 0; j < 4; j++) acc[i][j] = 0.f;

    int ar = tid >> 1, akq = (tid & 1) * 8;
    int bn = tid >> 2, bkq = (tid & 3) * 4;
    bool bvalid = (n0 + bn) < N;
    const float* Xp = X + (size_t)(row0 + ar) * 256 + akq;
    const float* Wp = W + (size_t)(bvalid ? (n0 + bn) : 0) * 256 + bkq;

    for (int kt = 0; kt < 16; kt++) {
        int k0 = kt * 16;
        float4 a0 = *(const float4*)(Xp + k0);
        float4 a1 = *(const float4*)(Xp + k0 + 4);
        float4 b0 = bvalid ? *(const float4*)(Wp + k0) : make_float4(0.f, 0.f, 0.f, 0.f);
        As[akq + 0][ar] = a0.x; As[akq + 1][ar] = a0.y;
        As[akq + 2][ar] = a0.z; As[akq + 3][ar] = a0.w;
        As[akq + 4][ar] = a1.x; As[akq + 5][ar] = a1.y;
        As[akq + 6][ar] = a1.z; As[akq + 7][ar] = a1.w;
        Bs[bkq + 0][bn] = b0.x; Bs[bkq + 1][bn] = b0.y;
        Bs[bkq + 2][bn] = b0.z; Bs[bkq + 3][bn] = b0.w;
        __syncthreads();
#pragma unroll
        for (int kk = 0; kk < 16; kk++) {
            float4 av0 = *(const float4*)&As[kk][rg * 8];
            float4 av1 = *(const float4*)&As[kk][rg * 8 + 4];
            float4 bv  = *(const float4*)&Bs[kk][cg * 4];
            float a[8] = {av0.x, av0.y, av0.z, av0.w, av1.x, av1.y, av1.z, av1.w};
            float bb[4] = {bv.x, bv.y, bv.z, bv.w};
#pragma unroll
            for (int i = 0; i < 8; i++)
#pragma unroll
                for (int j = 0; j < 4; j++) acc[i][j] = fmaf(a[i], bb[j], acc[i][j]);
        }
        __syncthreads();
    }
    int nc = n0 + cg * 4;
    if (nc < N) {
        float4 bb = *(const float4*)(bias + nc);
#pragma unroll
        for (int i = 0; i < 8; i++) {
            float4 o;
            o.x = acc[i][0] + bb.x; o.y = acc[i][1] + bb.y;
            o.z = acc[i][2] + bb.z; o.w = acc[i][3] + bb.w;
            *(float4*)(Y + (size_t)(row0 + rg * 8 + i) * N + nc) = o;
        }
    }
}

// ---- fp16 HMMA final projection: Y[32768x256] = S(half) @ W^T + bias ----
__global__ __launch_bounds__(256) void gemm_hmma(const __half* __restrict__ X,
                                                 const float* __restrict__ W,
                                                 const float* __restrict__ bias,
                                                 float* __restrict__ Y) {
    __shared__ __half Ah[128][40];
    __shared__ __half Bh[64][40];
    int tid = threadIdx.x;
    int row0 = blockIdx.y * 128, n0b = blockIdx.x * 64;
    int w = tid >> 5, lane = tid & 31, grp = lane >> 2, qid = lane & 3;
    float acc[8][4];
#pragma unroll
    for (int j = 0; j < 8; j++)
#pragma unroll
        for (int i = 0; i < 4; i++) acc[j][i] = 0.f;

    int ar = tid >> 1, aseg = (tid & 1) * 16;
    int br = tid >> 2, bq = (tid & 3) * 8;
    const __half* Xp = X + (size_t)(row0 + ar) * 256 + aseg;
    const float* Wp = W + (size_t)(n0b + br) * 256 + bq;

    for (int kt = 0; kt < 8; kt++) {
        int k0t = kt * 32;
        {
            uint4 v0 = *(const uint4*)(Xp + k0t);
            uint4 v1 = *(const uint4*)(Xp + k0t + 8);
            *(uint4*)&Ah[ar][aseg] = v0;
            *(uint4*)&Ah[ar][aseg + 8] = v1;
        }
        {
            float4 v0 = *(const float4*)(Wp + k0t);
            float4 v1 = *(const float4*)(Wp + k0t + 4);
            __half2 h[4];
            h[0] = __floats2half2_rn(v0.x, v0.y); h[1] = __floats2half2_rn(v0.z, v0.w);
            h[2] = __floats2half2_rn(v1.x, v1.y); h[3] = __floats2half2_rn(v1.z, v1.w);
            *(uint4*)&Bh[br][bq] = *(uint4*)h;
        }
        __syncthreads();
#pragma unroll
        for (int ks = 0; ks < 2; ks++) {
            int k0 = ks * 16;
            uint32_t a0 = *(const uint32_t*)&Ah[w * 16 + grp][k0 + qid * 2];
            uint32_t a1 = *(const uint32_t*)&Ah[w * 16 + grp + 8][k0 + qid * 2];
            uint32_t a2 = *(const uint32_t*)&Ah[w * 16 + grp][k0 + qid * 2 + 8];
            uint32_t a3 = *(const uint32_t*)&Ah[w * 16 + grp + 8][k0 + qid * 2 + 8];
#pragma unroll
            for (int j = 0; j < 8; j++) {
                uint32_t b0 = *(const uint32_t*)&Bh[j * 8 + grp][k0 + qid * 2];
                uint32_t b1 = *(const uint32_t*)&Bh[j * 8 + grp][k0 + qid * 2 + 8];
                asm volatile(
                    "mma.sync.aligned.m16n8k16.row.col.f32.f16.f16.f32 "
                    "{%0,%1,%2,%3}, {%4,%5,%6,%7}, {%8,%9}, {%0,%1,%2,%3};"
                    : "+f"(acc[j][0]), "+f"(acc[j][1]), "+f"(acc[j][2]), "+f"(acc[j][3])
                    : "r"(a0), "r"(a1), "r"(a2), "r"(a3), "r"(b0), "r"(b1));
            }
        }
        __syncthreads();
    }
    int r = row0 + w * 16 + grp;
#pragma unroll
    for (int j = 0; j < 8; j++) {
        int c = n0b + j * 8 + qid * 2;
        float2 bb = *(const float2*)(bias + c);
        float2 o0 = {acc[j][0] + bb.x, acc[j][1] + bb.y};
        float2 o1 = {acc[j][2] + bb.x, acc[j][3] + bb.y};
        *(float2*)(Y + (size_t)r * 256 + c) = o0;
        *(float2*)(Y + (size_t)(r + 8) * 256 + c) = o1;
    }
}

// ---- value (B,C,H,W) fp32 -> (B,H,W,C) fp16 ----
__global__ __launch_bounds__(256) void k_transpose(const float* __restrict__ val) {
    __shared__ float tile[32][33];
    int tx = threadIdx.x, ty = threadIdx.y;
    int b = blockIdx.z, y = blockIdx.y;
    int c0 = (blockIdx.x >> 2) * 32, x0 = (blockIdx.x & 3) * 32;
#pragma unroll
    for (int i = 0; i < 4; i++)
        tile[ty + i * 8][tx] = val[(((size_t)(b * Cdim + c0 + ty + i * 8) * Hh + y) * Ww) + x0 + tx];
    __syncthreads();
#pragma unroll
    for (int i = 0; i < 4; i++)
        g_vt[(((size_t)(b * Hh + y) * Ww + x0 + ty + i * 8) * Cdim) + c0 + tx] =
            __float2half(tile[tx][ty + i * 8]);
}

// ---- bilinear corner accumulate (fp16 values, fp32 math) ----
__device__ __forceinline__ void corner(const __half* __restrict__ vb, int x, int y,
                                       int moff, float w, float* acc) {
    if (x < 0 || x >= Ww || y < 0 || y >= Hh) return;
    const uint4* p = (const uint4*)(vb + ((size_t)(y * Ww + x)) * Cdim + moff);
#pragma unroll
    for (int i = 0; i < 4; i++) {
        uint4 u = p[i];
        const __half2* h = (const __half2*)&u;
#pragma unroll
        for (int j = 0; j < 4; j++) {
            float2 f = __half22float2(h[j]);
            acc[i * 8 + j * 2]     = fmaf(w, f.x, acc[i * 8 + j * 2]);
            acc[i * 8 + j * 2 + 1] = fmaf(w, f.y, acc[i * 8 + j * 2 + 1]);
        }
    }
}

// ---- deformable sampling: thread = (query, m); scrambled fp16 store into g_S ----
__global__ __launch_bounds__(128) void k_sample(const float* __restrict__ refp) {
    int bi = blockIdx.x;            // 2048 = B * 8 * 64
    int tid = threadIdx.x;
    int b = bi >> 9;
    int m = (bi >> 6) & 7;
    int gg = (bi & 63) * 128 + tid;
    int gh = gg >> 8, gl = gg & 255;
    size_t qidx = (size_t)b * NG + gg;
    float rx = refp[qidx * 2], ry = refp[qidx * 2 + 1];
    const float* oar = g_oa + qidx * 96;

    float a0 = oar[64 + m * 4], a1 = oar[64 + m * 4 + 1];
    float a2 = oar[64 + m * 4 + 2], a3 = oar[64 + m * 4 + 3];
    float amx = fmaxf(fmaxf(a0, a1), fmaxf(a2, a3));
    float e0 = __expf(a0 - amx), e1 = __expf(a1 - amx);
    float e2 = __expf(a2 - amx), e3 = __expf(a3 - amx);
    float inv = 1.f / (e0 + e1 + e2 + e3);
    float aw[4] = {e0 * inv, e1 * inv, e2 * inv, e3 * inv};

    const __half* vb = g_vt + (size_t)b * Hh * Ww * Cdim;
    float acc[32];
#pragma unroll
    for (int i = 0; i < 32; i++) acc[i] = 0.f;

#pragma unroll
    for (int p = 0; p < 4; p++) {
        float gx = (rx + oar[m * 8 + p * 2]) * (float)Ww - 0.5f;
        float gy = (ry + oar[m * 8 + p * 2 + 1]) * (float)Hh - 0.5f;
        float x0f = floorf(gx), y0f = floorf(gy);
        float fx = gx - x0f, fy = gy - y0f;
        int x0 = (int)x0f, y0 = (int)y0f;
        float w = aw[p];
        corner(vb, x0,     y0,     m * 32, (1.f - fx) * (1.f - fy) * w, acc);
        corner(vb, x0 + 1, y0,     m * 32, fx * (1.f - fy) * w, acc);
        corner(vb, x0,     y0 + 1, m * 32, (1.f - fx) * fy * w, acc);
        corner(vb, x0 + 1, y0 + 1, m * 32, fx * fy * w, acc);
    }
    // S[b][ch*256 + m*32 + gh][gl]  (fp16)
    __half* S = g_S + (size_t)b * NG * 256 + (size_t)(m * 32 + gh) * 256 + gl;
#pragma unroll
    for (int ch = 0; ch < 32; ch++) S[(size_t)ch * 65536] = __float2half(acc[ch]);
}

extern "C" void kernel_launch(void* const* d_in, const int* in_sizes, int n_in,
                              void* d_out, int out_size) {
    const float* query  = (const float*)d_in[0];
    const float* value  = (const float*)d_in[1];
    const float* refp   = (const float*)d_in[2];
    const float* trajp  = (const float*)d_in[3];
    const float* in_w   = (const float*)d_in[4];
    const float* in_b   = (const float*)d_in[5];
    const float* mha_w  = (const float*)d_in[6];
    const float* mha_b  = (const float*)d_in[7];
    const float* ln_g   = (const float*)d_in[8];
    const float* ln_b   = (const float*)d_in[9];
    const float* traj_w = (const float*)d_in[10];
    const float* traj_b = (const float*)d_in[11];
    const float* offs_w = (const float*)d_in[12];
    const float* offs_b = (const float*)d_in[13];
    const float* attw_w = (const float*)d_in[14];
    const float* attw_b = (const float*)d_in[15];
    const float* out_w  = (const float*)d_in[16];
    const float* out_b  = (const float*)d_in[17];
    float* out = (float*)d_out;

    float *p_ctx, *p_oa, *p_wc, *p_bc;
    __half* p_S;
    cudaGetSymbolAddress((void**)&p_S,   g_S);
    cudaGetSymbolAddress((void**)&p_ctx, g_ctx);
    cudaGetSymbolAddress((void**)&p_oa,  g_oa);
    cudaGetSymbolAddress((void**)&p_wc,  g_wc);
    cudaGetSymbolAddress((void**)&p_bc,  g_bc);

    // (0) weight concat + rank-3 precomputes
    k_prep<<<97, 256>>>(offs_w, offs_b, attw_w, attw_b);
    k_precomp<<<6, 256>>>(in_w, in_b, traj_w, traj_b);
    k_precomp2<<<33, 256>>>(in_w, in_b, mha_w, mha_b);
    // (1) thin coef GEMM v3: coef[g,16] = query @ A^T + Ab
    k_coef<<<256, 256>>>(query);
    // (2) rank-3 attention -> g_R
    k_attn3<<<1024, 256>>>(trajp);
    // (3) fused mha-out(K=16) + residual + LN -> g_ctx
    k_ctxln<<<4096, 256>>>(query, ln_g, ln_b);
    // (4) offs + attw fused GEMM (scalar fp32), N=96
    gemm_bias<<<dim3(2, 256), 256>>>(p_ctx, p_wc, p_bc, p_oa, 96);
    // (5) value transpose to fp16 (B,H,W,C)
    k_transpose<<<dim3(32, 128, 4), dim3(32, 8)>>>(value);
    // (6) deformable sampling (fp16 scrambled S)
    k_sample<<<2048, 128>>>(refp);
    // (7) final projection via fp16 HMMA
    gemm_hmma<<<dim3(4, 256), 256>>>(p_S, out_w, out_b, out);
}